// round 10
// baseline (speedup 1.0000x reference)
#include <cuda_runtime.h>
#include <cuda_bf16.h>
#include <cstdint>

#define NMAX 100000
#define NPAD 100096
#define EMAX 1600000
#define H 128

// -------- scratch (device globals; no allocation allowed) --------
__device__ __nv_bfloat16 d_hb [(size_t)NPAD * H];  // node features (bf16; pad rows stay 0)
__device__ __nv_bfloat16 d_h2b[(size_t)NPAD * H];  // h @ W (bf16)
__device__ float         d_dis[NMAX];              // degree count -> rsqrt(deg+1)
__device__ int           d_rowstart[NMAX + 1];     // CSR row offsets (by dst)
__device__ int           d_cursor[NMAX];           // placement cursors
__device__ int2          d_edge[EMAX];             // packed (src, dis[src] bits)
__device__ float         d_bsum[64];               // scan block sums
__device__ uint32_t      d_wt[3 * H * H];          // fragment-ordered tf32 W images
__device__ float         d_g[H];                   // column sums for mean pool
__device__ int           d_is64;                   // edge_index is int64?

__device__ __forceinline__ uint32_t f2tf(float f) {
    uint32_t u;
    asm("cvt.rna.tf32.f32 %0, %1;" : "=r"(u) : "f"(f));
    return u;
}

#define MMA_TF32(c, a, b0, b1)                                                 \
    asm volatile("mma.sync.aligned.m16n8k8.row.col.f32.tf32.tf32.f32 "         \
        "{%0,%1,%2,%3}, {%4,%5,%6,%7}, {%8,%9}, {%0,%1,%2,%3};"                \
        : "+f"((c)[0]), "+f"((c)[1]), "+f"((c)[2]), "+f"((c)[3])               \
        : "r"((a)[0]), "r"((a)[1]), "r"((a)[2]), "r"((a)[3]),                  \
          "r"(b0), "r"(b1))

// ==================== preprocessing ====================
__global__ void detect_kernel(const int* ei, int E) {
    if (threadIdx.x == 0 && blockIdx.x == 0) {
        int n = E < 64 ? E : 64;
        int all0 = 1;
        for (int i = 0; i < n; i++)
            if (ei[2 * i + 1] != 0) { all0 = 0; break; }
        d_is64 = all0;
    }
}

// 4 edges per thread, vectorized dst loads
__global__ void degree_kernel(const void* ei, int E) {
    int t = blockIdx.x * blockDim.x + threadIdx.x;
    int e = t * 4;
    if (e + 4 <= E) {
        int d0, d1, d2, d3;
        if (d_is64) {
            const longlong2* p = (const longlong2*)((const long long*)ei + E + e);
            longlong2 a = p[0], b = p[1];
            d0 = (int)a.x; d1 = (int)a.y; d2 = (int)b.x; d3 = (int)b.y;
        } else {
            int4 v = *(const int4*)((const int*)ei + E + e);
            d0 = v.x; d1 = v.y; d2 = v.z; d3 = v.w;
        }
        atomicAdd(&d_dis[d0], 1.0f);
        atomicAdd(&d_dis[d1], 1.0f);
        atomicAdd(&d_dis[d2], 1.0f);
        atomicAdd(&d_dis[d3], 1.0f);
    } else {
        for (int k = e; k < E; k++) {
            int dst;
            if (d_is64) dst = (int)((const long long*)ei)[(long long)E + k];
            else        dst = ((const int*)ei)[E + k];
            atomicAdd(&d_dis[dst], 1.0f);
        }
    }
}

// -------- scan phase 1: per-block (2048 elems) exclusive prefix, block sum out --------
__global__ void scan_part(int N) {
    __shared__ float ss[1024];
    int b = blockIdx.x, tid = threadIdx.x;
    int i0 = b * 2048 + 2 * tid, i1 = i0 + 1;
    float a = (i0 < N) ? d_dis[i0] : 0.0f;
    float c = (i1 < N) ? d_dis[i1] : 0.0f;
    ss[tid] = a + c;
    __syncthreads();
    for (int off = 1; off < 1024; off <<= 1) {
        float v = (tid >= off) ? ss[tid - off] : 0.0f;
        __syncthreads();
        ss[tid] += v;
        __syncthreads();
    }
    float excl = (tid > 0) ? ss[tid - 1] : 0.0f;
    if (i0 < N) d_rowstart[i0] = (int)excl;
    if (i1 < N) d_rowstart[i1] = (int)(excl + a);
    if (tid == 1023) d_bsum[b] = ss[1023];
}

// -------- scan phase 2 (fused): apply block offsets; init cursor; dis transform --------
__global__ void scan_apply(int N, int E, int nb) {
    __shared__ float ss[65];
    int tid = threadIdx.x;  // 256
    if (tid == 0) {
        float r = 0.0f;
        for (int j = 0; j < nb; j++) { ss[j] = r; r += d_bsum[j]; }
    }
    __syncthreads();
    int i = blockIdx.x * blockDim.x + tid;
    if (i < N) {
        int r = d_rowstart[i] + (int)ss[i >> 11];
        d_rowstart[i] = r;
        d_cursor[i] = r;
        d_dis[i] = rsqrtf(d_dis[i] + 1.0f);
    }
    if (i == 0) d_rowstart[N] = E;
}

// 4 edges per thread, vectorized src/dst loads
__global__ void place_kernel(const void* ei, int E) {
    int t = blockIdx.x * blockDim.x + threadIdx.x;
    int e = t * 4;
    if (e + 4 <= E) {
        int s0, s1, s2, s3, d0, d1, d2, d3;
        if (d_is64) {
            const long long* p = (const long long*)ei;
            longlong2 sa = *(const longlong2*)(p + e);
            longlong2 sb = *(const longlong2*)(p + e + 2);
            longlong2 da = *(const longlong2*)(p + E + e);
            longlong2 db = *(const longlong2*)(p + E + e + 2);
            s0 = (int)sa.x; s1 = (int)sa.y; s2 = (int)sb.x; s3 = (int)sb.y;
            d0 = (int)da.x; d1 = (int)da.y; d2 = (int)db.x; d3 = (int)db.y;
        } else {
            const int* p = (const int*)ei;
            int4 sv = *(const int4*)(p + e);
            int4 dv = *(const int4*)(p + E + e);
            s0 = sv.x; s1 = sv.y; s2 = sv.z; s3 = sv.w;
            d0 = dv.x; d1 = dv.y; d2 = dv.z; d3 = dv.w;
        }
        float c0 = d_dis[s0], c1 = d_dis[s1], c2 = d_dis[s2], c3 = d_dis[s3];
        int p0 = atomicAdd(&d_cursor[d0], 1);
        int p1 = atomicAdd(&d_cursor[d1], 1);
        int p2 = atomicAdd(&d_cursor[d2], 1);
        int p3 = atomicAdd(&d_cursor[d3], 1);
        d_edge[p0] = make_int2(s0, __float_as_int(c0));
        d_edge[p1] = make_int2(s1, __float_as_int(c1));
        d_edge[p2] = make_int2(s2, __float_as_int(c2));
        d_edge[p3] = make_int2(s3, __float_as_int(c3));
    } else {
        for (int k = e; k < E; k++) {
            int src, dst;
            if (d_is64) {
                const long long* p = (const long long*)ei;
                src = (int)p[k]; dst = (int)p[(long long)E + k];
            } else {
                const int* p = (const int*)ei;
                src = p[k]; dst = p[E + k];
            }
            int pos = atomicAdd(&d_cursor[dst], 1);
            d_edge[pos] = make_int2(src, __float_as_int(d_dis[src]));
        }
    }
}

// -------- W prep: fragment-ordered tf32 images --------
__global__ void wprep_kernel(const float* __restrict__ conv_w) {
    int e = blockIdx.x * blockDim.x + threadIdx.x;  // float2 entry id
    if (e >= 3 * 8192) return;
    int lane = e & 31;
    int nt   = (e >> 5) & 7;
    int ks   = (e >> 8) & 3;
    int half = (e >> 10) & 1;
    int c    = (e >> 11) & 3;
    int l    = e >> 13;
    int kq = lane & 3, grp = lane >> 2;
    int k = c * 32 + ks * 8 + kq;
    int n = half * 64 + nt * 8 + grp;
    const float* W = conv_w + (size_t)l * H * H;
    d_wt[(size_t)e * 2 + 0] = f2tf(W[(size_t)k * H + n]);
    d_wt[(size_t)e * 2 + 1] = f2tf(W[(size_t)(k + 4) * H + n]);
}

// -------- embedding: h = x @ emb_w + emb_b --------
__global__ void embed_kernel(const float* __restrict__ x,
                             const float* __restrict__ W,
                             const float* __restrict__ b, int N) {
    __shared__ float ws[16][H];
    __shared__ float xs[32][16];
    int tid = threadIdx.x;  // 128
    for (int i = tid; i < 16 * H; i += 128) ws[i / H][i % H] = W[i];
    float bias = b[tid];
    int n0 = blockIdx.x * 32;
    int nodes = min(32, N - n0);
    for (int i = tid; i < nodes * 16; i += 128) xs[i / 16][i % 16] = x[(size_t)n0 * 16 + i];
    __syncthreads();
    for (int n = 0; n < nodes; n++) {
        float s = bias;
#pragma unroll
        for (int k = 0; k < 16; k++) s += xs[n][k] * ws[k][tid];
        d_hb[(size_t)(n0 + n) * H + tid] = __float2bfloat16(s);
    }
}

// ==================== mma.sync tf32 GEMM with register prefetch ====================
__global__ __launch_bounds__(256) void gemm_mma_kernel(int layer) {
    __shared__ uint32_t sA[128][36];
    __shared__ __align__(16) uint32_t sB[4096];
    int tid = threadIdx.x;
    int warp = tid >> 5, lane = tid & 31;
    int wm = warp >> 1, wn = warp & 1;
    int grp = lane >> 2, kq = lane & 3;
    int row0 = blockIdx.x * 128;
    const uint32_t* wt = d_wt + (size_t)layer * (H * H);

    int ra0 = tid >> 2, qa0 = tid & 3;
    int ra1 = (256 + tid) >> 2, qa1 = tid & 3;

    float acc[2][8][4];
#pragma unroll
    for (int t = 0; t < 2; t++)
#pragma unroll
        for (int nt = 0; nt < 8; nt++)
#pragma unroll
            for (int j = 0; j < 4; j++) acc[t][nt][j] = 0.0f;

    uint4 pa0, pa1, pb[4];
    pa0 = *(const uint4*)&d_hb[(size_t)(row0 + ra0) * H + qa0 * 8];
    pa1 = *(const uint4*)&d_hb[(size_t)(row0 + ra1) * H + qa1 * 8];
#pragma unroll
    for (int v = 0; v < 4; v++)
        pb[v] = *(const uint4*)&wt[(size_t)(v * 256 + tid) * 4];

    for (int c = 0; c < 4; c++) {
        {
            float2 p0 = __bfloat1622float2(*(__nv_bfloat162*)&pa0.x);
            float2 p1 = __bfloat1622float2(*(__nv_bfloat162*)&pa0.y);
            float2 p2 = __bfloat1622float2(*(__nv_bfloat162*)&pa0.z);
            float2 p3 = __bfloat1622float2(*(__nv_bfloat162*)&pa0.w);
            *(uint4*)&sA[ra0][qa0 * 8 + 0] = make_uint4(f2tf(p0.x), f2tf(p0.y), f2tf(p1.x), f2tf(p1.y));
            *(uint4*)&sA[ra0][qa0 * 8 + 4] = make_uint4(f2tf(p2.x), f2tf(p2.y), f2tf(p3.x), f2tf(p3.y));
            p0 = __bfloat1622float2(*(__nv_bfloat162*)&pa1.x);
            p1 = __bfloat1622float2(*(__nv_bfloat162*)&pa1.y);
            p2 = __bfloat1622float2(*(__nv_bfloat162*)&pa1.z);
            p3 = __bfloat1622float2(*(__nv_bfloat162*)&pa1.w);
            *(uint4*)&sA[ra1][qa1 * 8 + 0] = make_uint4(f2tf(p0.x), f2tf(p0.y), f2tf(p1.x), f2tf(p1.y));
            *(uint4*)&sA[ra1][qa1 * 8 + 4] = make_uint4(f2tf(p2.x), f2tf(p2.y), f2tf(p3.x), f2tf(p3.y));
#pragma unroll
            for (int v = 0; v < 4; v++)
                *(uint4*)&sB[(v * 256 + tid) * 4] = pb[v];
        }
        __syncthreads();
        if (c < 3) {
            pa0 = *(const uint4*)&d_hb[(size_t)(row0 + ra0) * H + (c + 1) * 32 + qa0 * 8];
            pa1 = *(const uint4*)&d_hb[(size_t)(row0 + ra1) * H + (c + 1) * 32 + qa1 * 8];
#pragma unroll
            for (int v = 0; v < 4; v++)
                pb[v] = *(const uint4*)&wt[(size_t)(c + 1) * 4096 + (size_t)(v * 256 + tid) * 4];
        }
#pragma unroll
        for (int ks = 0; ks < 4; ks++) {
            uint32_t a[2][4];
#pragma unroll
            for (int t = 0; t < 2; t++) {
                int ar = wm * 32 + t * 16 + grp;
                a[t][0] = sA[ar][ks * 8 + kq];
                a[t][1] = sA[ar + 8][ks * 8 + kq];
                a[t][2] = sA[ar][ks * 8 + kq + 4];
                a[t][3] = sA[ar + 8][ks * 8 + kq + 4];
            }
#pragma unroll
            for (int nt = 0; nt < 8; nt++) {
                uint2 b = *(const uint2*)&sB[(((wn * 4 + ks) * 8 + nt) * 32 + lane) * 2];
                MMA_TF32(acc[0][nt], a[0], b.x, b.y);
                MMA_TF32(acc[1][nt], a[1], b.x, b.y);
            }
        }
        __syncthreads();
    }
#pragma unroll
    for (int t = 0; t < 2; t++) {
        int r = row0 + wm * 32 + t * 16 + grp;
#pragma unroll
        for (int nt = 0; nt < 8; nt++) {
            int col = wn * 64 + nt * 8 + kq * 2;
            *(__nv_bfloat162*)&d_h2b[(size_t)r * H + col] =
                __float22bfloat162_rn(make_float2(acc[t][nt][0], acc[t][nt][1]));
            *(__nv_bfloat162*)&d_h2b[(size_t)(r + 8) * H + col] =
                __float22bfloat162_rn(make_float2(acc[t][nt][2], acc[t][nt][3]));
        }
    }
}

// -------- fused gather + combine: one warp per dst node, direct loads, unroll 8 --------
__device__ __forceinline__ void acc_row(int src, float cf, int lane,
                                        float& ax, float& ay, float& az, float& aw) {
    uint2 u = *(const uint2*)&d_h2b[(size_t)src * H + lane * 4];
    float2 p0 = __bfloat1622float2(*(__nv_bfloat162*)&u.x);
    float2 p1 = __bfloat1622float2(*(__nv_bfloat162*)&u.y);
    ax += p0.x * cf; ay += p0.y * cf; az += p1.x * cf; aw += p1.y * cf;
}

__global__ void gather_kernel(const float* __restrict__ b, int N) {
    int w = (blockIdx.x * blockDim.x + threadIdx.x) >> 5;
    if (w >= N) return;
    int lane = threadIdx.x & 31;
    int beg = d_rowstart[w], end = d_rowstart[w + 1];
    float ax = 0.f, ay = 0.f, az = 0.f, aw = 0.f;
    int i = beg;
    for (; i + 8 <= end; i += 8) {
        int2 e0 = d_edge[i],     e1 = d_edge[i + 1], e2 = d_edge[i + 2], e3 = d_edge[i + 3];
        int2 e4 = d_edge[i + 4], e5 = d_edge[i + 5], e6 = d_edge[i + 6], e7 = d_edge[i + 7];
        acc_row(e0.x, __int_as_float(e0.y), lane, ax, ay, az, aw);
        acc_row(e1.x, __int_as_float(e1.y), lane, ax, ay, az, aw);
        acc_row(e2.x, __int_as_float(e2.y), lane, ax, ay, az, aw);
        acc_row(e3.x, __int_as_float(e3.y), lane, ax, ay, az, aw);
        acc_row(e4.x, __int_as_float(e4.y), lane, ax, ay, az, aw);
        acc_row(e5.x, __int_as_float(e5.y), lane, ax, ay, az, aw);
        acc_row(e6.x, __int_as_float(e6.y), lane, ax, ay, az, aw);
        acc_row(e7.x, __int_as_float(e7.y), lane, ax, ay, az, aw);
    }
    for (; i + 2 <= end; i += 2) {
        int2 e0 = d_edge[i], e1 = d_edge[i + 1];
        acc_row(e0.x, __int_as_float(e0.y), lane, ax, ay, az, aw);
        acc_row(e1.x, __int_as_float(e1.y), lane, ax, ay, az, aw);
    }
    if (i < end) {
        int2 e0 = d_edge[i];
        acc_row(e0.x, __int_as_float(e0.y), lane, ax, ay, az, aw);
    }
    float dd = d_dis[w];
    float dd2 = dd * dd;
    uint2 us = *(const uint2*)&d_h2b[(size_t)w * H + lane * 4];
    float2 h0 = __bfloat1622float2(*(__nv_bfloat162*)&us.x);
    float2 h1 = __bfloat1622float2(*(__nv_bfloat162*)&us.y);
    float4 bb = *(const float4*)&b[lane * 4];
    __nv_bfloat162 o0 = __float22bfloat162_rn(make_float2(
        fmaxf(ax * dd + h0.x * dd2 + bb.x, 0.0f),
        fmaxf(ay * dd + h0.y * dd2 + bb.y, 0.0f)));
    __nv_bfloat162 o1 = __float22bfloat162_rn(make_float2(
        fmaxf(az * dd + h1.x * dd2 + bb.z, 0.0f),
        fmaxf(aw * dd + h1.y * dd2 + bb.w, 0.0f)));
    uint2 st;
    st.x = *(uint32_t*)&o0;
    st.y = *(uint32_t*)&o1;
    *(uint2*)&d_hb[(size_t)w * H + lane * 4] = st;
}

// -------- global mean pool: column sums into d_g --------
__global__ void colsum_kernel(int N) {
    int tid = threadIdx.x;  // 128 -> cols 2*tid, 2*tid+1
    float sx = 0.0f, sy = 0.0f;
    for (int n = blockIdx.x; n < N; n += gridDim.x) {
        float2 f = __bfloat1622float2(*(__nv_bfloat162*)&d_hb[(size_t)n * H + 2 * tid]);
        sx += f.x; sy += f.y;
    }
    atomicAdd(&d_g[2 * tid], sx);
    atomicAdd(&d_g[2 * tid + 1], sy);
}

// -------- MLP head --------
__global__ void head_kernel(const float* __restrict__ fc1w, const float* __restrict__ fc1b,
                            const float* __restrict__ fc2w, const float* __restrict__ fc2b,
                            float* __restrict__ out, int N) {
    __shared__ float sg[H], sg1[H];
    int tid = threadIdx.x;  // 128
    sg[tid] = d_g[tid] / (float)N;
    __syncthreads();
    float s = fc1b[tid];
#pragma unroll 16
    for (int k = 0; k < H; k++) s += sg[k] * fc1w[(size_t)k * H + tid];
    sg1[tid] = fmaxf(s, 0.0f);
    __syncthreads();
    if (tid < 64) {
        float o = fc2b[tid];
#pragma unroll 16
        for (int k = 0; k < H; k++) o += sg1[k] * fc2w[(size_t)k * 64 + tid];
        out[tid] = o;
    }
}

extern "C" void kernel_launch(void* const* d_in, const int* in_sizes, int n_in,
                              void* d_out, int out_size) {
    const float* x      = (const float*)d_in[0];
    const void*  ei     = d_in[1];
    const float* emb_w  = (const float*)d_in[2];
    const float* emb_b  = (const float*)d_in[3];
    const float* conv_w = (const float*)d_in[4];
    const float* conv_b = (const float*)d_in[5];
    const float* fc1_w  = (const float*)d_in[6];
    const float* fc1_b  = (const float*)d_in[7];
    const float* fc2_w  = (const float*)d_in[8];
    const float* fc2_b  = (const float*)d_in[9];
    float* out = (float*)d_out;

    int N = in_sizes[0] / 16;   // 100000
    int E = in_sizes[1] / 2;    // 1600000

    void *dis_p, *g_p;
    cudaGetSymbolAddress(&dis_p, d_dis);
    cudaGetSymbolAddress(&g_p, d_g);

    int nb = (N + 2047) / 2048;   // scan blocks (<= 64)
    int eb4 = (E + 4 * 256 - 1) / (4 * 256);
    int gblocks = (int)(((long long)N * 32 + 255) / 256);
    int gemmblocks = (N + 127) / 128;   // 782 -> exactly NPAD rows

    // fork: preprocessing chain on a side stream, concurrent with embed/wprep/gemm1.
    // Host-side stream/event setup happens only during capture (graph replay skips it).
    cudaStream_t s2;
    cudaStreamCreateWithFlags(&s2, cudaStreamNonBlocking);
    cudaEvent_t evF, evJ;
    cudaEventCreateWithFlags(&evF, cudaEventDisableTiming);
    cudaEventCreateWithFlags(&evJ, cudaEventDisableTiming);

    cudaEventRecord(evF, 0);
    cudaStreamWaitEvent(s2, evF, 0);

    // side stream: CSR construction
    cudaMemsetAsync(dis_p, 0, (size_t)N * sizeof(float), s2);
    detect_kernel<<<1, 32, 0, s2>>>((const int*)ei, E);
    degree_kernel<<<eb4, 256, 0, s2>>>(ei, E);
    scan_part<<<nb, 1024, 0, s2>>>(N);
    scan_apply<<<(N + 255) / 256, 256, 0, s2>>>(N, E, nb);
    place_kernel<<<eb4, 256, 0, s2>>>(ei, E);
    cudaEventRecord(evJ, s2);

    // main stream: dense track
    cudaMemsetAsync(g_p, 0, H * sizeof(float));
    wprep_kernel<<<96, 256>>>(conv_w);
    embed_kernel<<<(N + 31) / 32, 128>>>(x, emb_w, emb_b, N);
    gemm_mma_kernel<<<gemmblocks, 256>>>(0);

    cudaStreamWaitEvent(0, evJ, 0);   // join: gather needs CSR + dis

    gather_kernel<<<gblocks, 256>>>(conv_b + 0 * H, N);
    for (int l = 1; l < 3; l++) {
        gemm_mma_kernel<<<gemmblocks, 256>>>(l);
        gather_kernel<<<gblocks, 256>>>(conv_b + (size_t)l * H, N);
    }

    colsum_kernel<<<512, 128>>>(N);
    head_kernel<<<1, 128>>>(fc1_w, fc1_b, fc2_w, fc2_b, out, N);
}

// round 11
// speedup vs baseline: 1.4662x; 1.4662x over previous
#include <cuda_runtime.h>
#include <cuda_bf16.h>
#include <cstdint>

#define NMAX 100000
#define NPAD 100096
#define EMAX 1600000
#define H 128

// -------- scratch (device globals; no allocation allowed) --------
__device__ __nv_bfloat16 d_hb [(size_t)NPAD * H];  // node features (bf16; pad rows stay 0)
__device__ __nv_bfloat16 d_h2b[(size_t)NPAD * H];  // h @ W (bf16)
__device__ float         d_dis[NMAX];              // degree count -> rsqrt(deg+1)
__device__ int           d_rowstart[NMAX + 1];     // CSR row offsets (by dst)
__device__ int           d_cursor[NMAX];           // placement cursors
__device__ int2          d_edge[EMAX];             // packed (src, dis[src] bits)
__device__ float         d_bsum[64];               // scan block sums
__device__ uint32_t      d_wt[3 * H * H];          // fragment-ordered tf32 W images
__device__ float         d_g[H];                   // column sums for mean pool
__device__ int           d_is64;                   // edge_index is int64?

__device__ __forceinline__ uint32_t f2tf(float f) {
    uint32_t u;
    asm("cvt.rna.tf32.f32 %0, %1;" : "=r"(u) : "f"(f));
    return u;
}

#define MMA_TF32(c, a, b0, b1)                                                 \
    asm volatile("mma.sync.aligned.m16n8k8.row.col.f32.tf32.tf32.f32 "         \
        "{%0,%1,%2,%3}, {%4,%5,%6,%7}, {%8,%9}, {%0,%1,%2,%3};"                \
        : "+f"((c)[0]), "+f"((c)[1]), "+f"((c)[2]), "+f"((c)[3])               \
        : "r"((a)[0]), "r"((a)[1]), "r"((a)[2]), "r"((a)[3]),                  \
          "r"(b0), "r"(b1))

// ==================== preprocessing ====================
__global__ void detect_kernel(const int* ei, int E) {
    if (threadIdx.x == 0 && blockIdx.x == 0) {
        int n = E < 64 ? E : 64;
        int all0 = 1;
        for (int i = 0; i < n; i++)
            if (ei[2 * i + 1] != 0) { all0 = 0; break; }
        d_is64 = all0;
    }
}

// 4 edges per thread, vectorized dst loads
__global__ void degree_kernel(const void* ei, int E) {
    int t = blockIdx.x * blockDim.x + threadIdx.x;
    int e = t * 4;
    if (e + 4 <= E) {
        int d0, d1, d2, d3;
        if (d_is64) {
            const longlong2* p = (const longlong2*)((const long long*)ei + E + e);
            longlong2 a = p[0], b = p[1];
            d0 = (int)a.x; d1 = (int)a.y; d2 = (int)b.x; d3 = (int)b.y;
        } else {
            int4 v = *(const int4*)((const int*)ei + E + e);
            d0 = v.x; d1 = v.y; d2 = v.z; d3 = v.w;
        }
        atomicAdd(&d_dis[d0], 1.0f);
        atomicAdd(&d_dis[d1], 1.0f);
        atomicAdd(&d_dis[d2], 1.0f);
        atomicAdd(&d_dis[d3], 1.0f);
    } else {
        for (int k = e; k < E; k++) {
            int dst;
            if (d_is64) dst = (int)((const long long*)ei)[(long long)E + k];
            else        dst = ((const int*)ei)[E + k];
            atomicAdd(&d_dis[dst], 1.0f);
        }
    }
}

// -------- scan phase 1: per-block (2048 elems) exclusive prefix, block sum out --------
__global__ void scan_part(int N) {
    __shared__ float ss[1024];
    int b = blockIdx.x, tid = threadIdx.x;
    int i0 = b * 2048 + 2 * tid, i1 = i0 + 1;
    float a = (i0 < N) ? d_dis[i0] : 0.0f;
    float c = (i1 < N) ? d_dis[i1] : 0.0f;
    ss[tid] = a + c;
    __syncthreads();
    for (int off = 1; off < 1024; off <<= 1) {
        float v = (tid >= off) ? ss[tid - off] : 0.0f;
        __syncthreads();
        ss[tid] += v;
        __syncthreads();
    }
    float excl = (tid > 0) ? ss[tid - 1] : 0.0f;
    if (i0 < N) d_rowstart[i0] = (int)excl;
    if (i1 < N) d_rowstart[i1] = (int)(excl + a);
    if (tid == 1023) d_bsum[b] = ss[1023];
}

// -------- scan phase 2 (fused): apply block offsets; init cursor; dis transform --------
__global__ void scan_apply(int N, int E, int nb) {
    __shared__ float ss[65];
    int tid = threadIdx.x;  // 256
    if (tid == 0) {
        float r = 0.0f;
        for (int j = 0; j < nb; j++) { ss[j] = r; r += d_bsum[j]; }
    }
    __syncthreads();
    int i = blockIdx.x * blockDim.x + tid;
    if (i < N) {
        int r = d_rowstart[i] + (int)ss[i >> 11];
        d_rowstart[i] = r;
        d_cursor[i] = r;
        d_dis[i] = rsqrtf(d_dis[i] + 1.0f);
    }
    if (i == 0) d_rowstart[N] = E;
}

// 4 edges per thread, vectorized src/dst loads
__global__ void place_kernel(const void* ei, int E) {
    int t = blockIdx.x * blockDim.x + threadIdx.x;
    int e = t * 4;
    if (e + 4 <= E) {
        int s0, s1, s2, s3, d0, d1, d2, d3;
        if (d_is64) {
            const long long* p = (const long long*)ei;
            longlong2 sa = *(const longlong2*)(p + e);
            longlong2 sb = *(const longlong2*)(p + e + 2);
            longlong2 da = *(const longlong2*)(p + E + e);
            longlong2 db = *(const longlong2*)(p + E + e + 2);
            s0 = (int)sa.x; s1 = (int)sa.y; s2 = (int)sb.x; s3 = (int)sb.y;
            d0 = (int)da.x; d1 = (int)da.y; d2 = (int)db.x; d3 = (int)db.y;
        } else {
            const int* p = (const int*)ei;
            int4 sv = *(const int4*)(p + e);
            int4 dv = *(const int4*)(p + E + e);
            s0 = sv.x; s1 = sv.y; s2 = sv.z; s3 = sv.w;
            d0 = dv.x; d1 = dv.y; d2 = dv.z; d3 = dv.w;
        }
        float c0 = d_dis[s0], c1 = d_dis[s1], c2 = d_dis[s2], c3 = d_dis[s3];
        int p0 = atomicAdd(&d_cursor[d0], 1);
        int p1 = atomicAdd(&d_cursor[d1], 1);
        int p2 = atomicAdd(&d_cursor[d2], 1);
        int p3 = atomicAdd(&d_cursor[d3], 1);
        d_edge[p0] = make_int2(s0, __float_as_int(c0));
        d_edge[p1] = make_int2(s1, __float_as_int(c1));
        d_edge[p2] = make_int2(s2, __float_as_int(c2));
        d_edge[p3] = make_int2(s3, __float_as_int(c3));
    } else {
        for (int k = e; k < E; k++) {
            int src, dst;
            if (d_is64) {
                const long long* p = (const long long*)ei;
                src = (int)p[k]; dst = (int)p[(long long)E + k];
            } else {
                const int* p = (const int*)ei;
                src = p[k]; dst = p[E + k];
            }
            int pos = atomicAdd(&d_cursor[dst], 1);
            d_edge[pos] = make_int2(src, __float_as_int(d_dis[src]));
        }
    }
}

// -------- W prep: fragment-ordered tf32 images --------
__global__ void wprep_kernel(const float* __restrict__ conv_w) {
    int e = blockIdx.x * blockDim.x + threadIdx.x;  // float2 entry id
    if (e >= 3 * 8192) return;
    int lane = e & 31;
    int nt   = (e >> 5) & 7;
    int ks   = (e >> 8) & 3;
    int half = (e >> 10) & 1;
    int c    = (e >> 11) & 3;
    int l    = e >> 13;
    int kq = lane & 3, grp = lane >> 2;
    int k = c * 32 + ks * 8 + kq;
    int n = half * 64 + nt * 8 + grp;
    const float* W = conv_w + (size_t)l * H * H;
    d_wt[(size_t)e * 2 + 0] = f2tf(W[(size_t)k * H + n]);
    d_wt[(size_t)e * 2 + 1] = f2tf(W[(size_t)(k + 4) * H + n]);
}

// -------- embedding: h = x @ emb_w + emb_b --------
__global__ void embed_kernel(const float* __restrict__ x,
                             const float* __restrict__ W,
                             const float* __restrict__ b, int N) {
    __shared__ float ws[16][H];
    __shared__ float xs[32][16];
    int tid = threadIdx.x;  // 128
    for (int i = tid; i < 16 * H; i += 128) ws[i / H][i % H] = W[i];
    float bias = b[tid];
    int n0 = blockIdx.x * 32;
    int nodes = min(32, N - n0);
    for (int i = tid; i < nodes * 16; i += 128) xs[i / 16][i % 16] = x[(size_t)n0 * 16 + i];
    __syncthreads();
    for (int n = 0; n < nodes; n++) {
        float s = bias;
#pragma unroll
        for (int k = 0; k < 16; k++) s += xs[n][k] * ws[k][tid];
        d_hb[(size_t)(n0 + n) * H + tid] = __float2bfloat16(s);
    }
}

// ==================== mma.sync tf32 GEMM with register prefetch ====================
__global__ __launch_bounds__(256) void gemm_mma_kernel(int layer) {
    __shared__ uint32_t sA[128][36];
    __shared__ __align__(16) uint32_t sB[4096];
    int tid = threadIdx.x;
    int warp = tid >> 5, lane = tid & 31;
    int wm = warp >> 1, wn = warp & 1;
    int grp = lane >> 2, kq = lane & 3;
    int row0 = blockIdx.x * 128;
    const uint32_t* wt = d_wt + (size_t)layer * (H * H);

    int ra0 = tid >> 2, qa0 = tid & 3;
    int ra1 = (256 + tid) >> 2, qa1 = tid & 3;

    float acc[2][8][4];
#pragma unroll
    for (int t = 0; t < 2; t++)
#pragma unroll
        for (int nt = 0; nt < 8; nt++)
#pragma unroll
            for (int j = 0; j < 4; j++) acc[t][nt][j] = 0.0f;

    uint4 pa0, pa1, pb[4];
    pa0 = *(const uint4*)&d_hb[(size_t)(row0 + ra0) * H + qa0 * 8];
    pa1 = *(const uint4*)&d_hb[(size_t)(row0 + ra1) * H + qa1 * 8];
#pragma unroll
    for (int v = 0; v < 4; v++)
        pb[v] = *(const uint4*)&wt[(size_t)(v * 256 + tid) * 4];

    for (int c = 0; c < 4; c++) {
        {
            float2 p0 = __bfloat1622float2(*(__nv_bfloat162*)&pa0.x);
            float2 p1 = __bfloat1622float2(*(__nv_bfloat162*)&pa0.y);
            float2 p2 = __bfloat1622float2(*(__nv_bfloat162*)&pa0.z);
            float2 p3 = __bfloat1622float2(*(__nv_bfloat162*)&pa0.w);
            *(uint4*)&sA[ra0][qa0 * 8 + 0] = make_uint4(f2tf(p0.x), f2tf(p0.y), f2tf(p1.x), f2tf(p1.y));
            *(uint4*)&sA[ra0][qa0 * 8 + 4] = make_uint4(f2tf(p2.x), f2tf(p2.y), f2tf(p3.x), f2tf(p3.y));
            p0 = __bfloat1622float2(*(__nv_bfloat162*)&pa1.x);
            p1 = __bfloat1622float2(*(__nv_bfloat162*)&pa1.y);
            p2 = __bfloat1622float2(*(__nv_bfloat162*)&pa1.z);
            p3 = __bfloat1622float2(*(__nv_bfloat162*)&pa1.w);
            *(uint4*)&sA[ra1][qa1 * 8 + 0] = make_uint4(f2tf(p0.x), f2tf(p0.y), f2tf(p1.x), f2tf(p1.y));
            *(uint4*)&sA[ra1][qa1 * 8 + 4] = make_uint4(f2tf(p2.x), f2tf(p2.y), f2tf(p3.x), f2tf(p3.y));
#pragma unroll
            for (int v = 0; v < 4; v++)
                *(uint4*)&sB[(v * 256 + tid) * 4] = pb[v];
        }
        __syncthreads();
        if (c < 3) {
            pa0 = *(const uint4*)&d_hb[(size_t)(row0 + ra0) * H + (c + 1) * 32 + qa0 * 8];
            pa1 = *(const uint4*)&d_hb[(size_t)(row0 + ra1) * H + (c + 1) * 32 + qa1 * 8];
#pragma unroll
            for (int v = 0; v < 4; v++)
                pb[v] = *(const uint4*)&wt[(size_t)(c + 1) * 4096 + (size_t)(v * 256 + tid) * 4];
        }
#pragma unroll
        for (int ks = 0; ks < 4; ks++) {
            uint32_t a[2][4];
#pragma unroll
            for (int t = 0; t < 2; t++) {
                int ar = wm * 32 + t * 16 + grp;
                a[t][0] = sA[ar][ks * 8 + kq];
                a[t][1] = sA[ar + 8][ks * 8 + kq];
                a[t][2] = sA[ar][ks * 8 + kq + 4];
                a[t][3] = sA[ar + 8][ks * 8 + kq + 4];
            }
#pragma unroll
            for (int nt = 0; nt < 8; nt++) {
                uint2 b = *(const uint2*)&sB[(((wn * 4 + ks) * 8 + nt) * 32 + lane) * 2];
                MMA_TF32(acc[0][nt], a[0], b.x, b.y);
                MMA_TF32(acc[1][nt], a[1], b.x, b.y);
            }
        }
        __syncthreads();
    }
#pragma unroll
    for (int t = 0; t < 2; t++) {
        int r = row0 + wm * 32 + t * 16 + grp;
#pragma unroll
        for (int nt = 0; nt < 8; nt++) {
            int col = wn * 64 + nt * 8 + kq * 2;
            *(__nv_bfloat162*)&d_h2b[(size_t)r * H + col] =
                __float22bfloat162_rn(make_float2(acc[t][nt][0], acc[t][nt][1]));
            *(__nv_bfloat162*)&d_h2b[(size_t)(r + 8) * H + col] =
                __float22bfloat162_rn(make_float2(acc[t][nt][2], acc[t][nt][3]));
        }
    }
}

// -------- fused gather + combine: one warp per dst node, direct loads, unroll 8 --------
__device__ __forceinline__ void acc_row(int src, float cf, int lane,
                                        float& ax, float& ay, float& az, float& aw) {
    uint2 u = *(const uint2*)&d_h2b[(size_t)src * H + lane * 4];
    float2 p0 = __bfloat1622float2(*(__nv_bfloat162*)&u.x);
    float2 p1 = __bfloat1622float2(*(__nv_bfloat162*)&u.y);
    ax += p0.x * cf; ay += p0.y * cf; az += p1.x * cf; aw += p1.y * cf;
}

__global__ void gather_kernel(const float* __restrict__ b, int N) {
    int w = (blockIdx.x * blockDim.x + threadIdx.x) >> 5;
    if (w >= N) return;
    int lane = threadIdx.x & 31;
    int beg = d_rowstart[w], end = d_rowstart[w + 1];
    float ax = 0.f, ay = 0.f, az = 0.f, aw = 0.f;
    int i = beg;
    for (; i + 8 <= end; i += 8) {
        int2 e0 = d_edge[i],     e1 = d_edge[i + 1], e2 = d_edge[i + 2], e3 = d_edge[i + 3];
        int2 e4 = d_edge[i + 4], e5 = d_edge[i + 5], e6 = d_edge[i + 6], e7 = d_edge[i + 7];
        acc_row(e0.x, __int_as_float(e0.y), lane, ax, ay, az, aw);
        acc_row(e1.x, __int_as_float(e1.y), lane, ax, ay, az, aw);
        acc_row(e2.x, __int_as_float(e2.y), lane, ax, ay, az, aw);
        acc_row(e3.x, __int_as_float(e3.y), lane, ax, ay, az, aw);
        acc_row(e4.x, __int_as_float(e4.y), lane, ax, ay, az, aw);
        acc_row(e5.x, __int_as_float(e5.y), lane, ax, ay, az, aw);
        acc_row(e6.x, __int_as_float(e6.y), lane, ax, ay, az, aw);
        acc_row(e7.x, __int_as_float(e7.y), lane, ax, ay, az, aw);
    }
    for (; i + 2 <= end; i += 2) {
        int2 e0 = d_edge[i], e1 = d_edge[i + 1];
        acc_row(e0.x, __int_as_float(e0.y), lane, ax, ay, az, aw);
        acc_row(e1.x, __int_as_float(e1.y), lane, ax, ay, az, aw);
    }
    if (i < end) {
        int2 e0 = d_edge[i];
        acc_row(e0.x, __int_as_float(e0.y), lane, ax, ay, az, aw);
    }
    float dd = d_dis[w];
    float dd2 = dd * dd;
    uint2 us = *(const uint2*)&d_h2b[(size_t)w * H + lane * 4];
    float2 h0 = __bfloat1622float2(*(__nv_bfloat162*)&us.x);
    float2 h1 = __bfloat1622float2(*(__nv_bfloat162*)&us.y);
    float4 bb = *(const float4*)&b[lane * 4];
    __nv_bfloat162 o0 = __float22bfloat162_rn(make_float2(
        fmaxf(ax * dd + h0.x * dd2 + bb.x, 0.0f),
        fmaxf(ay * dd + h0.y * dd2 + bb.y, 0.0f)));
    __nv_bfloat162 o1 = __float22bfloat162_rn(make_float2(
        fmaxf(az * dd + h1.x * dd2 + bb.z, 0.0f),
        fmaxf(aw * dd + h1.y * dd2 + bb.w, 0.0f)));
    uint2 st;
    st.x = *(uint32_t*)&o0;
    st.y = *(uint32_t*)&o1;
    *(uint2*)&d_hb[(size_t)w * H + lane * 4] = st;
}

// -------- global mean pool: column sums into d_g --------
__global__ void colsum_kernel(int N) {
    int tid = threadIdx.x;  // 128 -> cols 2*tid, 2*tid+1
    float sx = 0.0f, sy = 0.0f;
    for (int n = blockIdx.x; n < N; n += gridDim.x) {
        float2 f = __bfloat1622float2(*(__nv_bfloat162*)&d_hb[(size_t)n * H + 2 * tid]);
        sx += f.x; sy += f.y;
    }
    atomicAdd(&d_g[2 * tid], sx);
    atomicAdd(&d_g[2 * tid + 1], sy);
}

// -------- MLP head --------
__global__ void head_kernel(const float* __restrict__ fc1w, const float* __restrict__ fc1b,
                            const float* __restrict__ fc2w, const float* __restrict__ fc2b,
                            float* __restrict__ out, int N) {
    __shared__ float sg[H], sg1[H];
    int tid = threadIdx.x;  // 128
    sg[tid] = d_g[tid] / (float)N;
    __syncthreads();
    float s = fc1b[tid];
#pragma unroll 16
    for (int k = 0; k < H; k++) s += sg[k] * fc1w[(size_t)k * H + tid];
    sg1[tid] = fmaxf(s, 0.0f);
    __syncthreads();
    if (tid < 64) {
        float o = fc2b[tid];
#pragma unroll 16
        for (int k = 0; k < H; k++) o += sg1[k] * fc2w[(size_t)k * 64 + tid];
        out[tid] = o;
    }
}

extern "C" void kernel_launch(void* const* d_in, const int* in_sizes, int n_in,
                              void* d_out, int out_size) {
    const float* x      = (const float*)d_in[0];
    const void*  ei     = d_in[1];
    const float* emb_w  = (const float*)d_in[2];
    const float* emb_b  = (const float*)d_in[3];
    const float* conv_w = (const float*)d_in[4];
    const float* conv_b = (const float*)d_in[5];
    const float* fc1_w  = (const float*)d_in[6];
    const float* fc1_b  = (const float*)d_in[7];
    const float* fc2_w  = (const float*)d_in[8];
    const float* fc2_b  = (const float*)d_in[9];
    float* out = (float*)d_out;

    int N = in_sizes[0] / 16;   // 100000
    int E = in_sizes[1] / 2;    // 1600000

    void *dis_p, *g_p;
    cudaGetSymbolAddress(&dis_p, d_dis);
    cudaGetSymbolAddress(&g_p, d_g);

    int nb = (N + 2047) / 2048;   // scan blocks (<= 64)
    int eb4 = (E + 4 * 256 - 1) / (4 * 256);
    int gblocks = (int)(((long long)N * 32 + 255) / 256);
    int gemmblocks = (N + 127) / 128;   // 782 -> exactly NPAD rows

    // fork: preprocessing chain on a side stream, concurrent with embed/wprep/gemm1.
    // Host-side stream/event setup happens only during capture (graph replay skips it).
    cudaStream_t s2;
    cudaStreamCreateWithFlags(&s2, cudaStreamNonBlocking);
    cudaEvent_t evF, evJ;
    cudaEventCreateWithFlags(&evF, cudaEventDisableTiming);
    cudaEventCreateWithFlags(&evJ, cudaEventDisableTiming);

    cudaEventRecord(evF, 0);
    cudaStreamWaitEvent(s2, evF, 0);

    // side stream: CSR construction
    cudaMemsetAsync(dis_p, 0, (size_t)N * sizeof(float), s2);
    detect_kernel<<<1, 32, 0, s2>>>((const int*)ei, E);
    degree_kernel<<<eb4, 256, 0, s2>>>(ei, E);
    scan_part<<<nb, 1024, 0, s2>>>(N);
    scan_apply<<<(N + 255) / 256, 256, 0, s2>>>(N, E, nb);
    place_kernel<<<eb4, 256, 0, s2>>>(ei, E);
    cudaEventRecord(evJ, s2);

    // main stream: dense track
    cudaMemsetAsync(g_p, 0, H * sizeof(float));
    wprep_kernel<<<96, 256>>>(conv_w);
    embed_kernel<<<(N + 31) / 32, 128>>>(x, emb_w, emb_b, N);
    gemm_mma_kernel<<<gemmblocks, 256>>>(0);

    cudaStreamWaitEvent(0, evJ, 0);   // join: gather needs CSR + dis

    gather_kernel<<<gblocks, 256>>>(conv_b + 0 * H, N);
    for (int l = 1; l < 3; l++) {
        gemm_mma_kernel<<<gemmblocks, 256>>>(l);
        gather_kernel<<<gblocks, 256>>>(conv_b + (size_t)l * H, N);
    }

    colsum_kernel<<<512, 128>>>(N);
    head_kernel<<<1, 128>>>(fc1_w, fc1_b, fc2_w, fc2_b, out, N);
}

// round 12
// speedup vs baseline: 1.5785x; 1.0765x over previous
#include <cuda_runtime.h>
#include <cuda_bf16.h>
#include <cstdint>

#define NMAX 100000
#define NPAD 100096
#define EMAX 1600000
#define H 128

// -------- scratch (device globals; no allocation allowed) --------
__device__ __nv_bfloat16 d_hb [(size_t)NPAD * H];  // node features (bf16; pad rows stay 0)
__device__ __nv_bfloat16 d_h2b[(size_t)NPAD * H];  // h @ W (bf16)
__device__ float         d_dis[NMAX];              // degree count -> rsqrt(deg+1)
__device__ int           d_rowstart[NMAX + 1];     // CSR row offsets (by dst)
__device__ int           d_cursor[NMAX];           // placement cursors
__device__ int2          d_edge[EMAX];             // packed (src, dis[src] bits)
__device__ float         d_bsum[64];               // scan block sums
__device__ uint32_t      d_wt[3 * 8192];           // fragment-ordered bf16 W images
__device__ float         d_g[H];                   // column sums for mean pool
__device__ int           d_is64;                   // edge_index is int64?

#define MMA_BF16(c, a, b0, b1)                                                 \
    asm volatile("mma.sync.aligned.m16n8k16.row.col.f32.bf16.bf16.f32 "        \
        "{%0,%1,%2,%3}, {%4,%5,%6,%7}, {%8,%9}, {%0,%1,%2,%3};"                \
        : "+f"((c)[0]), "+f"((c)[1]), "+f"((c)[2]), "+f"((c)[3])               \
        : "r"((a)[0]), "r"((a)[1]), "r"((a)[2]), "r"((a)[3]),                  \
          "r"(b0), "r"(b1))

// ==================== preprocessing ====================
__global__ void detect_kernel(const int* ei, int E) {
    if (threadIdx.x == 0 && blockIdx.x == 0) {
        int n = E < 64 ? E : 64;
        int all0 = 1;
        for (int i = 0; i < n; i++)
            if (ei[2 * i + 1] != 0) { all0 = 0; break; }
        d_is64 = all0;
    }
}

// 4 edges per thread, vectorized dst loads
__global__ void degree_kernel(const void* ei, int E) {
    int t = blockIdx.x * blockDim.x + threadIdx.x;
    int e = t * 4;
    if (e + 4 <= E) {
        int d0, d1, d2, d3;
        if (d_is64) {
            const longlong2* p = (const longlong2*)((const long long*)ei + E + e);
            longlong2 a = p[0], b = p[1];
            d0 = (int)a.x; d1 = (int)a.y; d2 = (int)b.x; d3 = (int)b.y;
        } else {
            int4 v = *(const int4*)((const int*)ei + E + e);
            d0 = v.x; d1 = v.y; d2 = v.z; d3 = v.w;
        }
        atomicAdd(&d_dis[d0], 1.0f);
        atomicAdd(&d_dis[d1], 1.0f);
        atomicAdd(&d_dis[d2], 1.0f);
        atomicAdd(&d_dis[d3], 1.0f);
    } else {
        for (int k = e; k < E; k++) {
            int dst;
            if (d_is64) dst = (int)((const long long*)ei)[(long long)E + k];
            else        dst = ((const int*)ei)[E + k];
            atomicAdd(&d_dis[dst], 1.0f);
        }
    }
}

// -------- scan phase 1: per-block (2048 elems) exclusive prefix, block sum out --------
__global__ void scan_part(int N) {
    __shared__ float ss[1024];
    int b = blockIdx.x, tid = threadIdx.x;
    int i0 = b * 2048 + 2 * tid, i1 = i0 + 1;
    float a = (i0 < N) ? d_dis[i0] : 0.0f;
    float c = (i1 < N) ? d_dis[i1] : 0.0f;
    ss[tid] = a + c;
    __syncthreads();
    for (int off = 1; off < 1024; off <<= 1) {
        float v = (tid >= off) ? ss[tid - off] : 0.0f;
        __syncthreads();
        ss[tid] += v;
        __syncthreads();
    }
    float excl = (tid > 0) ? ss[tid - 1] : 0.0f;
    if (i0 < N) d_rowstart[i0] = (int)excl;
    if (i1 < N) d_rowstart[i1] = (int)(excl + a);
    if (tid == 1023) d_bsum[b] = ss[1023];
}

// -------- scan phase 2 (fused): apply block offsets; init cursor; dis transform --------
__global__ void scan_apply(int N, int E, int nb) {
    __shared__ float ss[65];
    int tid = threadIdx.x;  // 256
    if (tid == 0) {
        float r = 0.0f;
        for (int j = 0; j < nb; j++) { ss[j] = r; r += d_bsum[j]; }
    }
    __syncthreads();
    int i = blockIdx.x * blockDim.x + tid;
    if (i < N) {
        int r = d_rowstart[i] + (int)ss[i >> 11];
        d_rowstart[i] = r;
        d_cursor[i] = r;
        d_dis[i] = rsqrtf(d_dis[i] + 1.0f);
    }
    if (i == 0) d_rowstart[N] = E;
}

// 4 edges per thread, vectorized src/dst loads
__global__ void place_kernel(const void* ei, int E) {
    int t = blockIdx.x * blockDim.x + threadIdx.x;
    int e = t * 4;
    if (e + 4 <= E) {
        int s0, s1, s2, s3, d0, d1, d2, d3;
        if (d_is64) {
            const long long* p = (const long long*)ei;
            longlong2 sa = *(const longlong2*)(p + e);
            longlong2 sb = *(const longlong2*)(p + e + 2);
            longlong2 da = *(const longlong2*)(p + E + e);
            longlong2 db = *(const longlong2*)(p + E + e + 2);
            s0 = (int)sa.x; s1 = (int)sa.y; s2 = (int)sb.x; s3 = (int)sb.y;
            d0 = (int)da.x; d1 = (int)da.y; d2 = (int)db.x; d3 = (int)db.y;
        } else {
            const int* p = (const int*)ei;
            int4 sv = *(const int4*)(p + e);
            int4 dv = *(const int4*)(p + E + e);
            s0 = sv.x; s1 = sv.y; s2 = sv.z; s3 = sv.w;
            d0 = dv.x; d1 = dv.y; d2 = dv.z; d3 = dv.w;
        }
        float c0 = d_dis[s0], c1 = d_dis[s1], c2 = d_dis[s2], c3 = d_dis[s3];
        int p0 = atomicAdd(&d_cursor[d0], 1);
        int p1 = atomicAdd(&d_cursor[d1], 1);
        int p2 = atomicAdd(&d_cursor[d2], 1);
        int p3 = atomicAdd(&d_cursor[d3], 1);
        d_edge[p0] = make_int2(s0, __float_as_int(c0));
        d_edge[p1] = make_int2(s1, __float_as_int(c1));
        d_edge[p2] = make_int2(s2, __float_as_int(c2));
        d_edge[p3] = make_int2(s3, __float_as_int(c3));
    } else {
        for (int k = e; k < E; k++) {
            int src, dst;
            if (d_is64) {
                const long long* p = (const long long*)ei;
                src = (int)p[k]; dst = (int)p[(long long)E + k];
            } else {
                const int* p = (const int*)ei;
                src = p[k]; dst = p[E + k];
            }
            int pos = atomicAdd(&d_cursor[dst], 1);
            d_edge[pos] = make_int2(src, __float_as_int(d_dis[src]));
        }
    }
}

// -------- W prep: fragment-ordered bf16 images for m16n8k16 --------
// layout per layer (uint2 entries): [c(4)][half(2)][ks(2)][nt(8)][lane(32)]
// kq = lane&3, grp = lane>>2, k = c*32 + ks*16 + kq*2, n = half*64 + nt*8 + grp
// b0 = {W[k][n], W[k+1][n]}, b1 = {W[k+8][n], W[k+9][n]}
__global__ void wprep_kernel(const float* __restrict__ conv_w) {
    int e = blockIdx.x * blockDim.x + threadIdx.x;  // uint2 entry id
    if (e >= 3 * 4096) return;
    int lane = e & 31;
    int nt   = (e >> 5) & 7;
    int ks   = (e >> 8) & 1;
    int half = (e >> 9) & 1;
    int c    = (e >> 10) & 3;
    int l    = e >> 12;
    int kq = lane & 3, grp = lane >> 2;
    int k = c * 32 + ks * 16 + kq * 2;
    int n = half * 64 + nt * 8 + grp;
    const float* W = conv_w + (size_t)l * H * H;
    __nv_bfloat162 b0 = __floats2bfloat162_rn(W[(size_t)k * H + n], W[(size_t)(k + 1) * H + n]);
    __nv_bfloat162 b1 = __floats2bfloat162_rn(W[(size_t)(k + 8) * H + n], W[(size_t)(k + 9) * H + n]);
    d_wt[(size_t)e * 2 + 0] = *(uint32_t*)&b0;
    d_wt[(size_t)e * 2 + 1] = *(uint32_t*)&b1;
}

// -------- embedding: h = x @ emb_w + emb_b --------
__global__ void embed_kernel(const float* __restrict__ x,
                             const float* __restrict__ W,
                             const float* __restrict__ b, int N) {
    __shared__ float ws[16][H];
    __shared__ float xs[32][16];
    int tid = threadIdx.x;  // 128
    for (int i = tid; i < 16 * H; i += 128) ws[i / H][i % H] = W[i];
    float bias = b[tid];
    int n0 = blockIdx.x * 32;
    int nodes = min(32, N - n0);
    for (int i = tid; i < nodes * 16; i += 128) xs[i / 16][i % 16] = x[(size_t)n0 * 16 + i];
    __syncthreads();
    for (int n = 0; n < nodes; n++) {
        float s = bias;
#pragma unroll
        for (int k = 0; k < 16; k++) s += xs[n][k] * ws[k][tid];
        d_hb[(size_t)(n0 + n) * H + tid] = __float2bfloat16(s);
    }
}

// ==================== mma.sync bf16 GEMM (m16n8k16) with register prefetch ====================
__global__ __launch_bounds__(256) void gemm_mma_kernel(int layer) {
    __shared__ uint32_t sA[128][20];                 // bf16 pairs; stride 20 -> conflict-free
    __shared__ __align__(16) uint32_t sB[2048];      // fragment-ordered bf16 W chunk
    int tid = threadIdx.x;
    int warp = tid >> 5, lane = tid & 31;
    int wm = warp >> 1, wn = warp & 1;
    int grp = lane >> 2, kq = lane & 3;
    int row0 = blockIdx.x * 128;
    const uint32_t* wt = d_wt + (size_t)layer * 8192;

    // A staging coords: idx in [0,512), 4 uint4 per row (16 pairs/row)
    int ra0 = tid >> 2, qa0 = tid & 3;               // idx = tid
    int ra1 = 64 + (tid >> 2), qa1 = tid & 3;        // idx = tid + 256

    float acc[2][8][4];
#pragma unroll
    for (int t = 0; t < 2; t++)
#pragma unroll
        for (int nt = 0; nt < 8; nt++)
#pragma unroll
            for (int j = 0; j < 4; j++) acc[t][nt][j] = 0.0f;

    uint4 pa0, pa1, pb[2];
    pa0 = *(const uint4*)&d_hb[(size_t)(row0 + ra0) * H + qa0 * 8];
    pa1 = *(const uint4*)&d_hb[(size_t)(row0 + ra1) * H + qa1 * 8];
#pragma unroll
    for (int v = 0; v < 2; v++)
        pb[v] = *(const uint4*)&wt[(size_t)(v * 256 + tid) * 4];

    for (int c = 0; c < 4; c++) {
        // store staged chunk (direct bf16 copy, no conversion)
        *(uint4*)&sA[ra0][qa0 * 4] = pa0;
        *(uint4*)&sA[ra1][qa1 * 4] = pa1;
#pragma unroll
        for (int v = 0; v < 2; v++)
            *(uint4*)&sB[(v * 256 + tid) * 4] = pb[v];
        __syncthreads();
        // prefetch next chunk while computing this one
        if (c < 3) {
            pa0 = *(const uint4*)&d_hb[(size_t)(row0 + ra0) * H + (c + 1) * 32 + qa0 * 8];
            pa1 = *(const uint4*)&d_hb[(size_t)(row0 + ra1) * H + (c + 1) * 32 + qa1 * 8];
#pragma unroll
            for (int v = 0; v < 2; v++)
                pb[v] = *(const uint4*)&wt[(size_t)(c + 1) * 2048 + (size_t)(v * 256 + tid) * 4];
        }
#pragma unroll
        for (int ks = 0; ks < 2; ks++) {
            uint32_t a[2][4];
#pragma unroll
            for (int t = 0; t < 2; t++) {
                int ar = wm * 32 + t * 16 + grp;
                a[t][0] = sA[ar][ks * 8 + kq];
                a[t][1] = sA[ar + 8][ks * 8 + kq];
                a[t][2] = sA[ar][ks * 8 + kq + 4];
                a[t][3] = sA[ar + 8][ks * 8 + kq + 4];
            }
#pragma unroll
            for (int nt = 0; nt < 8; nt++) {
                uint2 b = *(const uint2*)&sB[((((wn * 2 + ks) * 8) + nt) * 32 + lane) * 2];
                MMA_BF16(acc[0][nt], a[0], b.x, b.y);
                MMA_BF16(acc[1][nt], a[1], b.x, b.y);
            }
        }
        __syncthreads();
    }
#pragma unroll
    for (int t = 0; t < 2; t++) {
        int r = row0 + wm * 32 + t * 16 + grp;
#pragma unroll
        for (int nt = 0; nt < 8; nt++) {
            int col = wn * 64 + nt * 8 + kq * 2;
            *(__nv_bfloat162*)&d_h2b[(size_t)r * H + col] =
                __float22bfloat162_rn(make_float2(acc[t][nt][0], acc[t][nt][1]));
            *(__nv_bfloat162*)&d_h2b[(size_t)(r + 8) * H + col] =
                __float22bfloat162_rn(make_float2(acc[t][nt][2], acc[t][nt][3]));
        }
    }
}

// -------- fused gather + combine: one warp per dst node, direct loads, unroll 8 --------
__device__ __forceinline__ void acc_row(int src, float cf, int lane,
                                        float& ax, float& ay, float& az, float& aw) {
    uint2 u = *(const uint2*)&d_h2b[(size_t)src * H + lane * 4];
    float2 p0 = __bfloat1622float2(*(__nv_bfloat162*)&u.x);
    float2 p1 = __bfloat1622float2(*(__nv_bfloat162*)&u.y);
    ax += p0.x * cf; ay += p0.y * cf; az += p1.x * cf; aw += p1.y * cf;
}

__global__ void gather_kernel(const float* __restrict__ b, int N) {
    int w = (blockIdx.x * blockDim.x + threadIdx.x) >> 5;
    if (w >= N) return;
    int lane = threadIdx.x & 31;
    int beg = d_rowstart[w], end = d_rowstart[w + 1];
    float ax = 0.f, ay = 0.f, az = 0.f, aw = 0.f;
    int i = beg;
    for (; i + 8 <= end; i += 8) {
        int2 e0 = d_edge[i],     e1 = d_edge[i + 1], e2 = d_edge[i + 2], e3 = d_edge[i + 3];
        int2 e4 = d_edge[i + 4], e5 = d_edge[i + 5], e6 = d_edge[i + 6], e7 = d_edge[i + 7];
        acc_row(e0.x, __int_as_float(e0.y), lane, ax, ay, az, aw);
        acc_row(e1.x, __int_as_float(e1.y), lane, ax, ay, az, aw);
        acc_row(e2.x, __int_as_float(e2.y), lane, ax, ay, az, aw);
        acc_row(e3.x, __int_as_float(e3.y), lane, ax, ay, az, aw);
        acc_row(e4.x, __int_as_float(e4.y), lane, ax, ay, az, aw);
        acc_row(e5.x, __int_as_float(e5.y), lane, ax, ay, az, aw);
        acc_row(e6.x, __int_as_float(e6.y), lane, ax, ay, az, aw);
        acc_row(e7.x, __int_as_float(e7.y), lane, ax, ay, az, aw);
    }
    for (; i + 2 <= end; i += 2) {
        int2 e0 = d_edge[i], e1 = d_edge[i + 1];
        acc_row(e0.x, __int_as_float(e0.y), lane, ax, ay, az, aw);
        acc_row(e1.x, __int_as_float(e1.y), lane, ax, ay, az, aw);
    }
    if (i < end) {
        int2 e0 = d_edge[i];
        acc_row(e0.x, __int_as_float(e0.y), lane, ax, ay, az, aw);
    }
    float dd = d_dis[w];
    float dd2 = dd * dd;
    uint2 us = *(const uint2*)&d_h2b[(size_t)w * H + lane * 4];
    float2 h0 = __bfloat1622float2(*(__nv_bfloat162*)&us.x);
    float2 h1 = __bfloat1622float2(*(__nv_bfloat162*)&us.y);
    float4 bb = *(const float4*)&b[lane * 4];
    __nv_bfloat162 o0 = __float22bfloat162_rn(make_float2(
        fmaxf(ax * dd + h0.x * dd2 + bb.x, 0.0f),
        fmaxf(ay * dd + h0.y * dd2 + bb.y, 0.0f)));
    __nv_bfloat162 o1 = __float22bfloat162_rn(make_float2(
        fmaxf(az * dd + h1.x * dd2 + bb.z, 0.0f),
        fmaxf(aw * dd + h1.y * dd2 + bb.w, 0.0f)));
    uint2 st;
    st.x = *(uint32_t*)&o0;
    st.y = *(uint32_t*)&o1;
    *(uint2*)&d_hb[(size_t)w * H + lane * 4] = st;
}

// -------- global mean pool: column sums into d_g --------
__global__ void colsum_kernel(int N) {
    int tid = threadIdx.x;  // 128 -> cols 2*tid, 2*tid+1
    float sx = 0.0f, sy = 0.0f;
    for (int n = blockIdx.x; n < N; n += gridDim.x) {
        float2 f = __bfloat1622float2(*(__nv_bfloat162*)&d_hb[(size_t)n * H + 2 * tid]);
        sx += f.x; sy += f.y;
    }
    atomicAdd(&d_g[2 * tid], sx);
    atomicAdd(&d_g[2 * tid + 1], sy);
}

// -------- MLP head --------
__global__ void head_kernel(const float* __restrict__ fc1w, const float* __restrict__ fc1b,
                            const float* __restrict__ fc2w, const float* __restrict__ fc2b,
                            float* __restrict__ out, int N) {
    __shared__ float sg[H], sg1[H];
    int tid = threadIdx.x;  // 128
    sg[tid] = d_g[tid] / (float)N;
    __syncthreads();
    float s = fc1b[tid];
#pragma unroll 16
    for (int k = 0; k < H; k++) s += sg[k] * fc1w[(size_t)k * H + tid];
    sg1[tid] = fmaxf(s, 0.0f);
    __syncthreads();
    if (tid < 64) {
        float o = fc2b[tid];
#pragma unroll 16
        for (int k = 0; k < H; k++) o += sg1[k] * fc2w[(size_t)k * 64 + tid];
        out[tid] = o;
    }
}

extern "C" void kernel_launch(void* const* d_in, const int* in_sizes, int n_in,
                              void* d_out, int out_size) {
    const float* x      = (const float*)d_in[0];
    const void*  ei     = d_in[1];
    const float* emb_w  = (const float*)d_in[2];
    const float* emb_b  = (const float*)d_in[3];
    const float* conv_w = (const float*)d_in[4];
    const float* conv_b = (const float*)d_in[5];
    const float* fc1_w  = (const float*)d_in[6];
    const float* fc1_b  = (const float*)d_in[7];
    const float* fc2_w  = (const float*)d_in[8];
    const float* fc2_b  = (const float*)d_in[9];
    float* out = (float*)d_out;

    int N = in_sizes[0] / 16;   // 100000
    int E = in_sizes[1] / 2;    // 1600000

    void *dis_p, *g_p;
    cudaGetSymbolAddress(&dis_p, d_dis);
    cudaGetSymbolAddress(&g_p, d_g);

    int nb = (N + 2047) / 2048;   // scan blocks (<= 64)
    int eb4 = (E + 4 * 256 - 1) / (4 * 256);
    int gblocks = (int)(((long long)N * 32 + 255) / 256);
    int gemmblocks = (N + 127) / 128;   // 782 -> exactly NPAD rows

    // fork: preprocessing chain on a side stream, concurrent with embed/wprep/gemm1.
    cudaStream_t s2;
    cudaStreamCreateWithFlags(&s2, cudaStreamNonBlocking);
    cudaEvent_t evF, evJ;
    cudaEventCreateWithFlags(&evF, cudaEventDisableTiming);
    cudaEventCreateWithFlags(&evJ, cudaEventDisableTiming);

    cudaEventRecord(evF, 0);
    cudaStreamWaitEvent(s2, evF, 0);

    // side stream: CSR construction
    cudaMemsetAsync(dis_p, 0, (size_t)N * sizeof(float), s2);
    detect_kernel<<<1, 32, 0, s2>>>((const int*)ei, E);
    degree_kernel<<<eb4, 256, 0, s2>>>(ei, E);
    scan_part<<<nb, 1024, 0, s2>>>(N);
    scan_apply<<<(N + 255) / 256, 256, 0, s2>>>(N, E, nb);
    place_kernel<<<eb4, 256, 0, s2>>>(ei, E);
    cudaEventRecord(evJ, s2);

    // main stream: dense track
    cudaMemsetAsync(g_p, 0, H * sizeof(float));
    wprep_kernel<<<48, 256>>>(conv_w);
    embed_kernel<<<(N + 31) / 32, 128>>>(x, emb_w, emb_b, N);
    gemm_mma_kernel<<<gemmblocks, 256>>>(0);

    cudaStreamWaitEvent(0, evJ, 0);   // join: gather needs CSR + dis

    gather_kernel<<<gblocks, 256>>>(conv_b + 0 * H, N);
    for (int l = 1; l < 3; l++) {
        gemm_mma_kernel<<<gemmblocks, 256>>>(l);
        gather_kernel<<<gblocks, 256>>>(conv_b + (size_t)l * H, N);
    }

    colsum_kernel<<<512, 128>>>(N);
    head_kernel<<<1, 128>>>(fc1_w, fc1_b, fc2_w, fc2_b, out, N);
}

// round 13
// speedup vs baseline: 1.7939x; 1.1365x over previous
#include <cuda_runtime.h>
#include <cuda_bf16.h>
#include <cuda_fp16.h>
#include <cstdint>

#define NMAX 100000
#define NPAD 100096
#define EMAX 1600000
#define H 128

// -------- scratch (device globals; no allocation allowed) --------
__device__ __nv_bfloat16 d_hb [(size_t)NPAD * H];  // node features (bf16; pad rows stay 0)
__device__ uint8_t       d_h2f8[(size_t)NPAD * H]; // h @ W (fp8 e4m3) — sole h2 image
__device__ float         d_dis[NMAX];              // degree count -> rsqrt(deg+1)
__device__ int           d_rowstart[NMAX + 1];     // CSR row offsets (by dst)
__device__ int           d_cursor[NMAX];           // placement cursors
__device__ int2          d_edge[EMAX];             // packed (src, dis[src] bits)
__device__ float         d_bsum[64];               // scan block sums
__device__ uint32_t      d_wt[3 * 8192];           // fragment-ordered bf16 W images
__device__ float         d_g[H];                   // column sums for mean pool
__device__ int           d_is64;                   // edge_index is int64?

// pack two floats -> e4m3x2 (lo in low byte; verified orientation in R9)
__device__ __forceinline__ uint16_t pack_e4m3x2(float lo, float hi) {
    uint16_t r;
    asm("cvt.rn.satfinite.e4m3x2.f32 %0, %1, %2;" : "=h"(r) : "f"(hi), "f"(lo));
    return r;
}
__device__ __forceinline__ __half2 unpack_e4m3x2_h2(uint16_t w) {
    uint32_t h;
    asm("cvt.rn.f16x2.e4m3x2 %0, %1;" : "=r"(h) : "h"(w));
    return *reinterpret_cast<__half2*>(&h);
}

#define MMA_BF16(c, a, b0, b1)                                                 \
    asm volatile("mma.sync.aligned.m16n8k16.row.col.f32.bf16.bf16.f32 "        \
        "{%0,%1,%2,%3}, {%4,%5,%6,%7}, {%8,%9}, {%0,%1,%2,%3};"                \
        : "+f"((c)[0]), "+f"((c)[1]), "+f"((c)[2]), "+f"((c)[3])               \
        : "r"((a)[0]), "r"((a)[1]), "r"((a)[2]), "r"((a)[3]),                  \
          "r"(b0), "r"(b1))

// ==================== preprocessing ====================
__global__ void detect_kernel(const int* ei, int E) {
    if (threadIdx.x == 0 && blockIdx.x == 0) {
        int n = E < 64 ? E : 64;
        int all0 = 1;
        for (int i = 0; i < n; i++)
            if (ei[2 * i + 1] != 0) { all0 = 0; break; }
        d_is64 = all0;
    }
}

__global__ void degree_kernel(const void* ei, int E) {
    int t = blockIdx.x * blockDim.x + threadIdx.x;
    int e = t * 4;
    if (e + 4 <= E) {
        int d0, d1, d2, d3;
        if (d_is64) {
            const longlong2* p = (const longlong2*)((const long long*)ei + E + e);
            longlong2 a = p[0], b = p[1];
            d0 = (int)a.x; d1 = (int)a.y; d2 = (int)b.x; d3 = (int)b.y;
        } else {
            int4 v = *(const int4*)((const int*)ei + E + e);
            d0 = v.x; d1 = v.y; d2 = v.z; d3 = v.w;
        }
        atomicAdd(&d_dis[d0], 1.0f);
        atomicAdd(&d_dis[d1], 1.0f);
        atomicAdd(&d_dis[d2], 1.0f);
        atomicAdd(&d_dis[d3], 1.0f);
    } else {
        for (int k = e; k < E; k++) {
            int dst;
            if (d_is64) dst = (int)((const long long*)ei)[(long long)E + k];
            else        dst = ((const int*)ei)[E + k];
            atomicAdd(&d_dis[dst], 1.0f);
        }
    }
}

__global__ void scan_part(int N) {
    __shared__ float ss[1024];
    int b = blockIdx.x, tid = threadIdx.x;
    int i0 = b * 2048 + 2 * tid, i1 = i0 + 1;
    float a = (i0 < N) ? d_dis[i0] : 0.0f;
    float c = (i1 < N) ? d_dis[i1] : 0.0f;
    ss[tid] = a + c;
    __syncthreads();
    for (int off = 1; off < 1024; off <<= 1) {
        float v = (tid >= off) ? ss[tid - off] : 0.0f;
        __syncthreads();
        ss[tid] += v;
        __syncthreads();
    }
    float excl = (tid > 0) ? ss[tid - 1] : 0.0f;
    if (i0 < N) d_rowstart[i0] = (int)excl;
    if (i1 < N) d_rowstart[i1] = (int)(excl + a);
    if (tid == 1023) d_bsum[b] = ss[1023];
}

__global__ void scan_apply(int N, int E, int nb) {
    __shared__ float ss[65];
    int tid = threadIdx.x;  // 256
    if (tid == 0) {
        float r = 0.0f;
        for (int j = 0; j < nb; j++) { ss[j] = r; r += d_bsum[j]; }
    }
    __syncthreads();
    int i = blockIdx.x * blockDim.x + tid;
    if (i < N) {
        int r = d_rowstart[i] + (int)ss[i >> 11];
        d_rowstart[i] = r;
        d_cursor[i] = r;
        d_dis[i] = rsqrtf(d_dis[i] + 1.0f);
    }
    if (i == 0) d_rowstart[N] = E;
}

__global__ void place_kernel(const void* ei, int E) {
    int t = blockIdx.x * blockDim.x + threadIdx.x;
    int e = t * 4;
    if (e + 4 <= E) {
        int s0, s1, s2, s3, d0, d1, d2, d3;
        if (d_is64) {
            const long long* p = (const long long*)ei;
            longlong2 sa = *(const longlong2*)(p + e);
            longlong2 sb = *(const longlong2*)(p + e + 2);
            longlong2 da = *(const longlong2*)(p + E + e);
            longlong2 db = *(const longlong2*)(p + E + e + 2);
            s0 = (int)sa.x; s1 = (int)sa.y; s2 = (int)sb.x; s3 = (int)sb.y;
            d0 = (int)da.x; d1 = (int)da.y; d2 = (int)db.x; d3 = (int)db.y;
        } else {
            const int* p = (const int*)ei;
            int4 sv = *(const int4*)(p + e);
            int4 dv = *(const int4*)(p + E + e);
            s0 = sv.x; s1 = sv.y; s2 = sv.z; s3 = sv.w;
            d0 = dv.x; d1 = dv.y; d2 = dv.z; d3 = dv.w;
        }
        float c0 = d_dis[s0], c1 = d_dis[s1], c2 = d_dis[s2], c3 = d_dis[s3];
        int p0 = atomicAdd(&d_cursor[d0], 1);
        int p1 = atomicAdd(&d_cursor[d1], 1);
        int p2 = atomicAdd(&d_cursor[d2], 1);
        int p3 = atomicAdd(&d_cursor[d3], 1);
        d_edge[p0] = make_int2(s0, __float_as_int(c0));
        d_edge[p1] = make_int2(s1, __float_as_int(c1));
        d_edge[p2] = make_int2(s2, __float_as_int(c2));
        d_edge[p3] = make_int2(s3, __float_as_int(c3));
    } else {
        for (int k = e; k < E; k++) {
            int src, dst;
            if (d_is64) {
                const long long* p = (const long long*)ei;
                src = (int)p[k]; dst = (int)p[(long long)E + k];
            } else {
                const int* p = (const int*)ei;
                src = p[k]; dst = p[E + k];
            }
            int pos = atomicAdd(&d_cursor[dst], 1);
            d_edge[pos] = make_int2(src, __float_as_int(d_dis[src]));
        }
    }
}

// -------- W prep: fragment-ordered bf16 images for m16n8k16 --------
__global__ void wprep_kernel(const float* __restrict__ conv_w) {
    int e = blockIdx.x * blockDim.x + threadIdx.x;  // uint2 entry id
    if (e >= 3 * 4096) return;
    int lane = e & 31;
    int nt   = (e >> 5) & 7;
    int ks   = (e >> 8) & 1;
    int half = (e >> 9) & 1;
    int c    = (e >> 10) & 3;
    int l    = e >> 12;
    int kq = lane & 3, grp = lane >> 2;
    int k = c * 32 + ks * 16 + kq * 2;
    int n = half * 64 + nt * 8 + grp;
    const float* W = conv_w + (size_t)l * H * H;
    __nv_bfloat162 b0 = __floats2bfloat162_rn(W[(size_t)k * H + n], W[(size_t)(k + 1) * H + n]);
    __nv_bfloat162 b1 = __floats2bfloat162_rn(W[(size_t)(k + 8) * H + n], W[(size_t)(k + 9) * H + n]);
    d_wt[(size_t)e * 2 + 0] = *(uint32_t*)&b0;
    d_wt[(size_t)e * 2 + 1] = *(uint32_t*)&b1;
}

// -------- embedding: h = x @ emb_w + emb_b --------
__global__ void embed_kernel(const float* __restrict__ x,
                             const float* __restrict__ W,
                             const float* __restrict__ b, int N) {
    __shared__ float ws[16][H];
    __shared__ float xs[32][16];
    int tid = threadIdx.x;  // 128
    for (int i = tid; i < 16 * H; i += 128) ws[i / H][i % H] = W[i];
    float bias = b[tid];
    int n0 = blockIdx.x * 32;
    int nodes = min(32, N - n0);
    for (int i = tid; i < nodes * 16; i += 128) xs[i / 16][i % 16] = x[(size_t)n0 * 16 + i];
    __syncthreads();
    for (int n = 0; n < nodes; n++) {
        float s = bias;
#pragma unroll
        for (int k = 0; k < 16; k++) s += xs[n][k] * ws[k][tid];
        d_hb[(size_t)(n0 + n) * H + tid] = __float2bfloat16(s);
    }
}

// ==================== mma.sync bf16 GEMM (m16n8k16), fp8 epilogue ====================
__global__ __launch_bounds__(256) void gemm_mma_kernel(int layer) {
    __shared__ uint32_t sA[128][20];
    __shared__ __align__(16) uint32_t sB[2048];
    int tid = threadIdx.x;
    int warp = tid >> 5, lane = tid & 31;
    int wm = warp >> 1, wn = warp & 1;
    int grp = lane >> 2, kq = lane & 3;
    int row0 = blockIdx.x * 128;
    const uint32_t* wt = d_wt + (size_t)layer * 8192;

    int ra0 = tid >> 2, qa0 = tid & 3;
    int ra1 = 64 + (tid >> 2), qa1 = tid & 3;

    float acc[2][8][4];
#pragma unroll
    for (int t = 0; t < 2; t++)
#pragma unroll
        for (int nt = 0; nt < 8; nt++)
#pragma unroll
            for (int j = 0; j < 4; j++) acc[t][nt][j] = 0.0f;

    uint4 pa0, pa1, pb[2];
    pa0 = *(const uint4*)&d_hb[(size_t)(row0 + ra0) * H + qa0 * 8];
    pa1 = *(const uint4*)&d_hb[(size_t)(row0 + ra1) * H + qa1 * 8];
#pragma unroll
    for (int v = 0; v < 2; v++)
        pb[v] = *(const uint4*)&wt[(size_t)(v * 256 + tid) * 4];

    for (int c = 0; c < 4; c++) {
        *(uint4*)&sA[ra0][qa0 * 4] = pa0;
        *(uint4*)&sA[ra1][qa1 * 4] = pa1;
#pragma unroll
        for (int v = 0; v < 2; v++)
            *(uint4*)&sB[(v * 256 + tid) * 4] = pb[v];
        __syncthreads();
        if (c < 3) {
            pa0 = *(const uint4*)&d_hb[(size_t)(row0 + ra0) * H + (c + 1) * 32 + qa0 * 8];
            pa1 = *(const uint4*)&d_hb[(size_t)(row0 + ra1) * H + (c + 1) * 32 + qa1 * 8];
#pragma unroll
            for (int v = 0; v < 2; v++)
                pb[v] = *(const uint4*)&wt[(size_t)(c + 1) * 2048 + (size_t)(v * 256 + tid) * 4];
        }
#pragma unroll
        for (int ks = 0; ks < 2; ks++) {
            uint32_t a[2][4];
#pragma unroll
            for (int t = 0; t < 2; t++) {
                int ar = wm * 32 + t * 16 + grp;
                a[t][0] = sA[ar][ks * 8 + kq];
                a[t][1] = sA[ar + 8][ks * 8 + kq];
                a[t][2] = sA[ar][ks * 8 + kq + 4];
                a[t][3] = sA[ar + 8][ks * 8 + kq + 4];
            }
#pragma unroll
            for (int nt = 0; nt < 8; nt++) {
                uint2 b = *(const uint2*)&sB[((((wn * 2 + ks) * 8) + nt) * 32 + lane) * 2];
                MMA_BF16(acc[0][nt], a[0], b.x, b.y);
                MMA_BF16(acc[1][nt], a[1], b.x, b.y);
            }
        }
        __syncthreads();
    }
#pragma unroll
    for (int t = 0; t < 2; t++) {
        int r = row0 + wm * 32 + t * 16 + grp;
#pragma unroll
        for (int nt = 0; nt < 8; nt++) {
            int col = wn * 64 + nt * 8 + kq * 2;
            *(uint16_t*)&d_h2f8[(size_t)r * H + col] = pack_e4m3x2(acc[t][nt][0], acc[t][nt][1]);
            *(uint16_t*)&d_h2f8[(size_t)(r + 8) * H + col] = pack_e4m3x2(acc[t][nt][2], acc[t][nt][3]);
        }
    }
}

// -------- fused gather + combine: fp8 rows, half2 accumulation, unroll 8 --------
__device__ __forceinline__ void acc_row(int src, float cf, int lane,
                                        __half2& a0, __half2& a1) {
    uint32_t u = *(const uint32_t*)&d_h2f8[(size_t)src * H + lane * 4];
    __half2 p0 = unpack_e4m3x2_h2((uint16_t)(u & 0xFFFFu));
    __half2 p1 = unpack_e4m3x2_h2((uint16_t)(u >> 16));
    __half2 c2 = __float2half2_rn(cf);
    a0 = __hfma2(p0, c2, a0);
    a1 = __hfma2(p1, c2, a1);
}

__global__ void gather_kernel(const float* __restrict__ b, int N) {
    int w = (blockIdx.x * blockDim.x + threadIdx.x) >> 5;
    if (w >= N) return;
    int lane = threadIdx.x & 31;
    int beg = d_rowstart[w], end = d_rowstart[w + 1];
    __half2 a0 = __float2half2_rn(0.0f), a1 = __float2half2_rn(0.0f);
    int i = beg;
    for (; i + 8 <= end; i += 8) {
        int2 e0 = d_edge[i],     e1 = d_edge[i + 1], e2 = d_edge[i + 2], e3 = d_edge[i + 3];
        int2 e4 = d_edge[i + 4], e5 = d_edge[i + 5], e6 = d_edge[i + 6], e7 = d_edge[i + 7];
        acc_row(e0.x, __int_as_float(e0.y), lane, a0, a1);
        acc_row(e1.x, __int_as_float(e1.y), lane, a0, a1);
        acc_row(e2.x, __int_as_float(e2.y), lane, a0, a1);
        acc_row(e3.x, __int_as_float(e3.y), lane, a0, a1);
        acc_row(e4.x, __int_as_float(e4.y), lane, a0, a1);
        acc_row(e5.x, __int_as_float(e5.y), lane, a0, a1);
        acc_row(e6.x, __int_as_float(e6.y), lane, a0, a1);
        acc_row(e7.x, __int_as_float(e7.y), lane, a0, a1);
    }
    for (; i + 2 <= end; i += 2) {
        int2 e0 = d_edge[i], e1 = d_edge[i + 1];
        acc_row(e0.x, __int_as_float(e0.y), lane, a0, a1);
        acc_row(e1.x, __int_as_float(e1.y), lane, a0, a1);
    }
    if (i < end) {
        int2 e0 = d_edge[i];
        acc_row(e0.x, __int_as_float(e0.y), lane, a0, a1);
    }
    float2 f0 = __half22float2(a0);
    float2 f1 = __half22float2(a1);
    float dd = d_dis[w];
    float dd2 = dd * dd;
    // self term from fp8 row
    uint32_t us = *(const uint32_t*)&d_h2f8[(size_t)w * H + lane * 4];
    float2 h0 = __half22float2(unpack_e4m3x2_h2((uint16_t)(us & 0xFFFFu)));
    float2 h1 = __half22float2(unpack_e4m3x2_h2((uint16_t)(us >> 16)));
    float4 bb = *(const float4*)&b[lane * 4];
    __nv_bfloat162 o0 = __float22bfloat162_rn(make_float2(
        fmaxf(f0.x * dd + h0.x * dd2 + bb.x, 0.0f),
        fmaxf(f0.y * dd + h0.y * dd2 + bb.y, 0.0f)));
    __nv_bfloat162 o1 = __float22bfloat162_rn(make_float2(
        fmaxf(f1.x * dd + h1.x * dd2 + bb.z, 0.0f),
        fmaxf(f1.y * dd + h1.y * dd2 + bb.w, 0.0f)));
    uint2 st;
    st.x = *(uint32_t*)&o0;
    st.y = *(uint32_t*)&o1;
    *(uint2*)&d_hb[(size_t)w * H + lane * 4] = st;
}

// -------- global mean pool: column sums into d_g --------
__global__ void colsum_kernel(int N) {
    int tid = threadIdx.x;  // 128 -> cols 2*tid, 2*tid+1
    float sx = 0.0f, sy = 0.0f;
    for (int n = blockIdx.x; n < N; n += gridDim.x) {
        float2 f = __bfloat1622float2(*(__nv_bfloat162*)&d_hb[(size_t)n * H + 2 * tid]);
        sx += f.x; sy += f.y;
    }
    atomicAdd(&d_g[2 * tid], sx);
    atomicAdd(&d_g[2 * tid + 1], sy);
}

// -------- MLP head --------
__global__ void head_kernel(const float* __restrict__ fc1w, const float* __restrict__ fc1b,
                            const float* __restrict__ fc2w, const float* __restrict__ fc2b,
                            float* __restrict__ out, int N) {
    __shared__ float sg[H], sg1[H];
    int tid = threadIdx.x;  // 128
    sg[tid] = d_g[tid] / (float)N;
    __syncthreads();
    float s = fc1b[tid];
#pragma unroll 16
    for (int k = 0; k < H; k++) s += sg[k] * fc1w[(size_t)k * H + tid];
    sg1[tid] = fmaxf(s, 0.0f);
    __syncthreads();
    if (tid < 64) {
        float o = fc2b[tid];
#pragma unroll 16
        for (int k = 0; k < H; k++) o += sg1[k] * fc2w[(size_t)k * 64 + tid];
        out[tid] = o;
    }
}

extern "C" void kernel_launch(void* const* d_in, const int* in_sizes, int n_in,
                              void* d_out, int out_size) {
    const float* x      = (const float*)d_in[0];
    const void*  ei     = d_in[1];
    const float* emb_w  = (const float*)d_in[2];
    const float* emb_b  = (const float*)d_in[3];
    const float* conv_w = (const float*)d_in[4];
    const float* conv_b = (const float*)d_in[5];
    const float* fc1_w  = (const float*)d_in[6];
    const float* fc1_b  = (const float*)d_in[7];
    const float* fc2_w  = (const float*)d_in[8];
    const float* fc2_b  = (const float*)d_in[9];
    float* out = (float*)d_out;

    int N = in_sizes[0] / 16;   // 100000
    int E = in_sizes[1] / 2;    // 1600000

    void *dis_p, *g_p;
    cudaGetSymbolAddress(&dis_p, d_dis);
    cudaGetSymbolAddress(&g_p, d_g);

    int nb = (N + 2047) / 2048;
    int eb4 = (E + 4 * 256 - 1) / (4 * 256);
    int gblocks = (int)(((long long)N * 32 + 255) / 256);
    int gemmblocks = (N + 127) / 128;

    cudaStream_t s2;
    cudaStreamCreateWithFlags(&s2, cudaStreamNonBlocking);
    cudaEvent_t evF, evJ;
    cudaEventCreateWithFlags(&evF, cudaEventDisableTiming);
    cudaEventCreateWithFlags(&evJ, cudaEventDisableTiming);

    cudaEventRecord(evF, 0);
    cudaStreamWaitEvent(s2, evF, 0);

    // side stream: CSR construction
    cudaMemsetAsync(dis_p, 0, (size_t)N * sizeof(float), s2);
    detect_kernel<<<1, 32, 0, s2>>>((const int*)ei, E);
    degree_kernel<<<eb4, 256, 0, s2>>>(ei, E);
    scan_part<<<nb, 1024, 0, s2>>>(N);
    scan_apply<<<(N + 255) / 256, 256, 0, s2>>>(N, E, nb);
    place_kernel<<<eb4, 256, 0, s2>>>(ei, E);
    cudaEventRecord(evJ, s2);

    // main stream: dense track
    cudaMemsetAsync(g_p, 0, H * sizeof(float));
    wprep_kernel<<<48, 256>>>(conv_w);
    embed_kernel<<<(N + 31) / 32, 128>>>(x, emb_w, emb_b, N);
    gemm_mma_kernel<<<gemmblocks, 256>>>(0);

    cudaStreamWaitEvent(0, evJ, 0);

    gather_kernel<<<gblocks, 256>>>(conv_b + 0 * H, N);
    for (int l = 1; l < 3; l++) {
        gemm_mma_kernel<<<gemmblocks, 256>>>(l);
        gather_kernel<<<gblocks, 256>>>(conv_b + (size_t)l * H, N);
    }

    colsum_kernel<<<512, 128>>>(N);
    head_kernel<<<1, 128>>>(fc1_w, fc1_b, fc2_w, fc2_b, out, N);
}

// round 14
// speedup vs baseline: 1.8141x; 1.0113x over previous
#include <cuda_runtime.h>
#include <cuda_bf16.h>
#include <cuda_fp16.h>
#include <cstdint>

#define NMAX 100000
#define NPAD 100096
#define EMAX 1600000
#define H 128

// -------- scratch (device globals; no allocation allowed) --------
__device__ __nv_bfloat16 d_hb [(size_t)NPAD * H];  // node features (bf16; pad rows stay 0)
__device__ uint8_t       d_h2f8[(size_t)NPAD * H]; // h @ W (fp8 e4m3) — sole h2 image
__device__ float         d_dis[NMAX];              // degree count -> rsqrt(deg+1)
__device__ int           d_rowstart[NMAX + 1];     // CSR row offsets (by dst)
__device__ int           d_cursor[NMAX];           // placement cursors
__device__ int2          d_edge[EMAX];             // packed (src, dis[src] bits)
__device__ float         d_bsum[64];               // scan block sums
__device__ uint32_t      d_wt[3 * 8192];           // fragment-ordered bf16 W images
__device__ float         d_g[H];                   // column sums for mean pool
__device__ int           d_is64;                   // edge_index is int64?

// pack two floats -> e4m3x2 (lo in low byte; verified orientation in R9)
__device__ __forceinline__ uint16_t pack_e4m3x2(float lo, float hi) {
    uint16_t r;
    asm("cvt.rn.satfinite.e4m3x2.f32 %0, %1, %2;" : "=h"(r) : "f"(hi), "f"(lo));
    return r;
}
__device__ __forceinline__ __half2 unpack_e4m3x2_h2(uint16_t w) {
    uint32_t h;
    asm("cvt.rn.f16x2.e4m3x2 %0, %1;" : "=r"(h) : "h"(w));
    return *reinterpret_cast<__half2*>(&h);
}

#define MMA_BF16(c, a, b0, b1)                                                 \
    asm volatile("mma.sync.aligned.m16n8k16.row.col.f32.bf16.bf16.f32 "        \
        "{%0,%1,%2,%3}, {%4,%5,%6,%7}, {%8,%9}, {%0,%1,%2,%3};"                \
        : "+f"((c)[0]), "+f"((c)[1]), "+f"((c)[2]), "+f"((c)[3])               \
        : "r"((a)[0]), "r"((a)[1]), "r"((a)[2]), "r"((a)[3]),                  \
          "r"(b0), "r"(b1))

// ==================== preprocessing ====================
__global__ void detect_kernel(const int* ei, int E) {
    if (threadIdx.x == 0 && blockIdx.x == 0) {
        int n = E < 64 ? E : 64;
        int all0 = 1;
        for (int i = 0; i < n; i++)
            if (ei[2 * i + 1] != 0) { all0 = 0; break; }
        d_is64 = all0;
    }
}

__global__ void degree_kernel(const void* ei, int E) {
    int t = blockIdx.x * blockDim.x + threadIdx.x;
    int e = t * 4;
    if (e + 4 <= E) {
        int d0, d1, d2, d3;
        if (d_is64) {
            const longlong2* p = (const longlong2*)((const long long*)ei + E + e);
            longlong2 a = p[0], b = p[1];
            d0 = (int)a.x; d1 = (int)a.y; d2 = (int)b.x; d3 = (int)b.y;
        } else {
            int4 v = *(const int4*)((const int*)ei + E + e);
            d0 = v.x; d1 = v.y; d2 = v.z; d3 = v.w;
        }
        atomicAdd(&d_dis[d0], 1.0f);
        atomicAdd(&d_dis[d1], 1.0f);
        atomicAdd(&d_dis[d2], 1.0f);
        atomicAdd(&d_dis[d3], 1.0f);
    } else {
        for (int k = e; k < E; k++) {
            int dst;
            if (d_is64) dst = (int)((const long long*)ei)[(long long)E + k];
            else        dst = ((const int*)ei)[E + k];
            atomicAdd(&d_dis[dst], 1.0f);
        }
    }
}

__global__ void scan_part(int N) {
    __shared__ float ss[1024];
    int b = blockIdx.x, tid = threadIdx.x;
    int i0 = b * 2048 + 2 * tid, i1 = i0 + 1;
    float a = (i0 < N) ? d_dis[i0] : 0.0f;
    float c = (i1 < N) ? d_dis[i1] : 0.0f;
    ss[tid] = a + c;
    __syncthreads();
    for (int off = 1; off < 1024; off <<= 1) {
        float v = (tid >= off) ? ss[tid - off] : 0.0f;
        __syncthreads();
        ss[tid] += v;
        __syncthreads();
    }
    float excl = (tid > 0) ? ss[tid - 1] : 0.0f;
    if (i0 < N) d_rowstart[i0] = (int)excl;
    if (i1 < N) d_rowstart[i1] = (int)(excl + a);
    if (tid == 1023) d_bsum[b] = ss[1023];
}

__global__ void scan_apply(int N, int E, int nb) {
    __shared__ float ss[65];
    int tid = threadIdx.x;  // 256
    if (tid == 0) {
        float r = 0.0f;
        for (int j = 0; j < nb; j++) { ss[j] = r; r += d_bsum[j]; }
    }
    __syncthreads();
    int i = blockIdx.x * blockDim.x + tid;
    if (i < N) {
        int r = d_rowstart[i] + (int)ss[i >> 11];
        d_rowstart[i] = r;
        d_cursor[i] = r;
        d_dis[i] = rsqrtf(d_dis[i] + 1.0f);
    }
    if (i == 0) d_rowstart[N] = E;
}

__global__ void place_kernel(const void* ei, int E) {
    int t = blockIdx.x * blockDim.x + threadIdx.x;
    int e = t * 4;
    if (e + 4 <= E) {
        int s0, s1, s2, s3, d0, d1, d2, d3;
        if (d_is64) {
            const long long* p = (const long long*)ei;
            longlong2 sa = *(const longlong2*)(p + e);
            longlong2 sb = *(const longlong2*)(p + e + 2);
            longlong2 da = *(const longlong2*)(p + E + e);
            longlong2 db = *(const longlong2*)(p + E + e + 2);
            s0 = (int)sa.x; s1 = (int)sa.y; s2 = (int)sb.x; s3 = (int)sb.y;
            d0 = (int)da.x; d1 = (int)da.y; d2 = (int)db.x; d3 = (int)db.y;
        } else {
            const int* p = (const int*)ei;
            int4 sv = *(const int4*)(p + e);
            int4 dv = *(const int4*)(p + E + e);
            s0 = sv.x; s1 = sv.y; s2 = sv.z; s3 = sv.w;
            d0 = dv.x; d1 = dv.y; d2 = dv.z; d3 = dv.w;
        }
        float c0 = d_dis[s0], c1 = d_dis[s1], c2 = d_dis[s2], c3 = d_dis[s3];
        int p0 = atomicAdd(&d_cursor[d0], 1);
        int p1 = atomicAdd(&d_cursor[d1], 1);
        int p2 = atomicAdd(&d_cursor[d2], 1);
        int p3 = atomicAdd(&d_cursor[d3], 1);
        d_edge[p0] = make_int2(s0, __float_as_int(c0));
        d_edge[p1] = make_int2(s1, __float_as_int(c1));
        d_edge[p2] = make_int2(s2, __float_as_int(c2));
        d_edge[p3] = make_int2(s3, __float_as_int(c3));
    } else {
        for (int k = e; k < E; k++) {
            int src, dst;
            if (d_is64) {
                const long long* p = (const long long*)ei;
                src = (int)p[k]; dst = (int)p[(long long)E + k];
            } else {
                const int* p = (const int*)ei;
                src = p[k]; dst = p[E + k];
            }
            int pos = atomicAdd(&d_cursor[dst], 1);
            d_edge[pos] = make_int2(src, __float_as_int(d_dis[src]));
        }
    }
}

// -------- W prep: fragment-ordered bf16 images for m16n8k16 --------
__global__ void wprep_kernel(const float* __restrict__ conv_w) {
    int e = blockIdx.x * blockDim.x + threadIdx.x;  // uint2 entry id
    if (e >= 3 * 4096) return;
    int lane = e & 31;
    int nt   = (e >> 5) & 7;
    int ks   = (e >> 8) & 1;
    int half = (e >> 9) & 1;
    int c    = (e >> 10) & 3;
    int l    = e >> 12;
    int kq = lane & 3, grp = lane >> 2;
    int k = c * 32 + ks * 16 + kq * 2;
    int n = half * 64 + nt * 8 + grp;
    const float* W = conv_w + (size_t)l * H * H;
    __nv_bfloat162 b0 = __floats2bfloat162_rn(W[(size_t)k * H + n], W[(size_t)(k + 1) * H + n]);
    __nv_bfloat162 b1 = __floats2bfloat162_rn(W[(size_t)(k + 8) * H + n], W[(size_t)(k + 9) * H + n]);
    d_wt[(size_t)e * 2 + 0] = *(uint32_t*)&b0;
    d_wt[(size_t)e * 2 + 1] = *(uint32_t*)&b1;
}

// -------- embedding: h = x @ emb_w + emb_b --------
__global__ void embed_kernel(const float* __restrict__ x,
                             const float* __restrict__ W,
                             const float* __restrict__ b, int N) {
    __shared__ float ws[16][H];
    __shared__ float xs[32][16];
    int tid = threadIdx.x;  // 128
    for (int i = tid; i < 16 * H; i += 128) ws[i / H][i % H] = W[i];
    float bias = b[tid];
    int n0 = blockIdx.x * 32;
    int nodes = min(32, N - n0);
    for (int i = tid; i < nodes * 16; i += 128) xs[i / 16][i % 16] = x[(size_t)n0 * 16 + i];
    __syncthreads();
    for (int n = 0; n < nodes; n++) {
        float s = bias;
#pragma unroll
        for (int k = 0; k < 16; k++) s += xs[n][k] * ws[k][tid];
        d_hb[(size_t)(n0 + n) * H + tid] = __float2bfloat16(s);
    }
}

// ==================== mma.sync bf16 GEMM (m16n8k16), fp8 epilogue ====================
__global__ __launch_bounds__(256) void gemm_mma_kernel(int layer) {
    __shared__ uint32_t sA[128][20];
    __shared__ __align__(16) uint32_t sB[2048];
    int tid = threadIdx.x;
    int warp = tid >> 5, lane = tid & 31;
    int wm = warp >> 1, wn = warp & 1;
    int grp = lane >> 2, kq = lane & 3;
    int row0 = blockIdx.x * 128;
    const uint32_t* wt = d_wt + (size_t)layer * 8192;

    int ra0 = tid >> 2, qa0 = tid & 3;
    int ra1 = 64 + (tid >> 2), qa1 = tid & 3;

    float acc[2][8][4];
#pragma unroll
    for (int t = 0; t < 2; t++)
#pragma unroll
        for (int nt = 0; nt < 8; nt++)
#pragma unroll
            for (int j = 0; j < 4; j++) acc[t][nt][j] = 0.0f;

    uint4 pa0, pa1, pb[2];
    pa0 = *(const uint4*)&d_hb[(size_t)(row0 + ra0) * H + qa0 * 8];
    pa1 = *(const uint4*)&d_hb[(size_t)(row0 + ra1) * H + qa1 * 8];
#pragma unroll
    for (int v = 0; v < 2; v++)
        pb[v] = *(const uint4*)&wt[(size_t)(v * 256 + tid) * 4];

    for (int c = 0; c < 4; c++) {
        *(uint4*)&sA[ra0][qa0 * 4] = pa0;
        *(uint4*)&sA[ra1][qa1 * 4] = pa1;
#pragma unroll
        for (int v = 0; v < 2; v++)
            *(uint4*)&sB[(v * 256 + tid) * 4] = pb[v];
        __syncthreads();
        if (c < 3) {
            pa0 = *(const uint4*)&d_hb[(size_t)(row0 + ra0) * H + (c + 1) * 32 + qa0 * 8];
            pa1 = *(const uint4*)&d_hb[(size_t)(row0 + ra1) * H + (c + 1) * 32 + qa1 * 8];
#pragma unroll
            for (int v = 0; v < 2; v++)
                pb[v] = *(const uint4*)&wt[(size_t)(c + 1) * 2048 + (size_t)(v * 256 + tid) * 4];
        }
#pragma unroll
        for (int ks = 0; ks < 2; ks++) {
            uint32_t a[2][4];
#pragma unroll
            for (int t = 0; t < 2; t++) {
                int ar = wm * 32 + t * 16 + grp;
                a[t][0] = sA[ar][ks * 8 + kq];
                a[t][1] = sA[ar + 8][ks * 8 + kq];
                a[t][2] = sA[ar][ks * 8 + kq + 4];
                a[t][3] = sA[ar + 8][ks * 8 + kq + 4];
            }
#pragma unroll
            for (int nt = 0; nt < 8; nt++) {
                uint2 b = *(const uint2*)&sB[((((wn * 2 + ks) * 8) + nt) * 32 + lane) * 2];
                MMA_BF16(acc[0][nt], a[0], b.x, b.y);
                MMA_BF16(acc[1][nt], a[1], b.x, b.y);
            }
        }
        __syncthreads();
    }
#pragma unroll
    for (int t = 0; t < 2; t++) {
        int r = row0 + wm * 32 + t * 16 + grp;
#pragma unroll
        for (int nt = 0; nt < 8; nt++) {
            int col = wn * 64 + nt * 8 + kq * 2;
            *(uint16_t*)&d_h2f8[(size_t)r * H + col] = pack_e4m3x2(acc[t][nt][0], acc[t][nt][1]);
            *(uint16_t*)&d_h2f8[(size_t)(r + 8) * H + col] = pack_e4m3x2(acc[t][nt][2], acc[t][nt][3]);
        }
    }
}

// -------- fused gather + combine: fp8 rows, half2 accumulation, unroll 8 --------
__device__ __forceinline__ void acc_row(int src, float cf, int lane,
                                        __half2& a0, __half2& a1) {
    uint32_t u = *(const uint32_t*)&d_h2f8[(size_t)src * H + lane * 4];
    __half2 p0 = unpack_e4m3x2_h2((uint16_t)(u & 0xFFFFu));
    __half2 p1 = unpack_e4m3x2_h2((uint16_t)(u >> 16));
    __half2 c2 = __float2half2_rn(cf);
    a0 = __hfma2(p0, c2, a0);
    a1 = __hfma2(p1, c2, a1);
}

__global__ void gather_kernel(const float* __restrict__ b, int N) {
    int w = (blockIdx.x * blockDim.x + threadIdx.x) >> 5;
    if (w >= N) return;
    int lane = threadIdx.x & 31;
    int beg = d_rowstart[w], end = d_rowstart[w + 1];
    __half2 a0 = __float2half2_rn(0.0f), a1 = __float2half2_rn(0.0f);
    int i = beg;
    for (; i + 8 <= end; i += 8) {
        int2 e0 = d_edge[i],     e1 = d_edge[i + 1], e2 = d_edge[i + 2], e3 = d_edge[i + 3];
        int2 e4 = d_edge[i + 4], e5 = d_edge[i + 5], e6 = d_edge[i + 6], e7 = d_edge[i + 7];
        acc_row(e0.x, __int_as_float(e0.y), lane, a0, a1);
        acc_row(e1.x, __int_as_float(e1.y), lane, a0, a1);
        acc_row(e2.x, __int_as_float(e2.y), lane, a0, a1);
        acc_row(e3.x, __int_as_float(e3.y), lane, a0, a1);
        acc_row(e4.x, __int_as_float(e4.y), lane, a0, a1);
        acc_row(e5.x, __int_as_float(e5.y), lane, a0, a1);
        acc_row(e6.x, __int_as_float(e6.y), lane, a0, a1);
        acc_row(e7.x, __int_as_float(e7.y), lane, a0, a1);
    }
    for (; i + 2 <= end; i += 2) {
        int2 e0 = d_edge[i], e1 = d_edge[i + 1];
        acc_row(e0.x, __int_as_float(e0.y), lane, a0, a1);
        acc_row(e1.x, __int_as_float(e1.y), lane, a0, a1);
    }
    if (i < end) {
        int2 e0 = d_edge[i];
        acc_row(e0.x, __int_as_float(e0.y), lane, a0, a1);
    }
    float2 f0 = __half22float2(a0);
    float2 f1 = __half22float2(a1);
    float dd = d_dis[w];
    float dd2 = dd * dd;
    // self term from fp8 row
    uint32_t us = *(const uint32_t*)&d_h2f8[(size_t)w * H + lane * 4];
    float2 h0 = __half22float2(unpack_e4m3x2_h2((uint16_t)(us & 0xFFFFu)));
    float2 h1 = __half22float2(unpack_e4m3x2_h2((uint16_t)(us >> 16)));
    float4 bb = *(const float4*)&b[lane * 4];
    __nv_bfloat162 o0 = __float22bfloat162_rn(make_float2(
        fmaxf(f0.x * dd + h0.x * dd2 + bb.x, 0.0f),
        fmaxf(f0.y * dd + h0.y * dd2 + bb.y, 0.0f)));
    __nv_bfloat162 o1 = __float22bfloat162_rn(make_float2(
        fmaxf(f1.x * dd + h1.x * dd2 + bb.z, 0.0f),
        fmaxf(f1.y * dd + h1.y * dd2 + bb.w, 0.0f)));
    uint2 st;
    st.x = *(uint32_t*)&o0;
    st.y = *(uint32_t*)&o1;
    *(uint2*)&d_hb[(size_t)w * H + lane * 4] = st;
}

// -------- global mean pool: column sums into d_g --------
__global__ void colsum_kernel(int N) {
    int tid = threadIdx.x;  // 128 -> cols 2*tid, 2*tid+1
    float sx = 0.0f, sy = 0.0f;
    for (int n = blockIdx.x; n < N; n += gridDim.x) {
        float2 f = __bfloat1622float2(*(__nv_bfloat162*)&d_hb[(size_t)n * H + 2 * tid]);
        sx += f.x; sy += f.y;
    }
    atomicAdd(&d_g[2 * tid], sx);
    atomicAdd(&d_g[2 * tid + 1], sy);
}

// -------- MLP head --------
__global__ void head_kernel(const float* __restrict__ fc1w, const float* __restrict__ fc1b,
                            const float* __restrict__ fc2w, const float* __restrict__ fc2b,
                            float* __restrict__ out, int N) {
    __shared__ float sg[H], sg1[H];
    int tid = threadIdx.x;  // 128
    sg[tid] = d_g[tid] / (float)N;
    __syncthreads();
    float s = fc1b[tid];
#pragma unroll 16
    for (int k = 0; k < H; k++) s += sg[k] * fc1w[(size_t)k * H + tid];
    sg1[tid] = fmaxf(s, 0.0f);
    __syncthreads();
    if (tid < 64) {
        float o = fc2b[tid];
#pragma unroll 16
        for (int k = 0; k < H; k++) o += sg1[k] * fc2w[(size_t)k * 64 + tid];
        out[tid] = o;
    }
}

extern "C" void kernel_launch(void* const* d_in, const int* in_sizes, int n_in,
                              void* d_out, int out_size) {
    const float* x      = (const float*)d_in[0];
    const void*  ei     = d_in[1];
    const float* emb_w  = (const float*)d_in[2];
    const float* emb_b  = (const float*)d_in[3];
    const float* conv_w = (const float*)d_in[4];
    const float* conv_b = (const float*)d_in[5];
    const float* fc1_w  = (const float*)d_in[6];
    const float* fc1_b  = (const float*)d_in[7];
    const float* fc2_w  = (const float*)d_in[8];
    const float* fc2_b  = (const float*)d_in[9];
    float* out = (float*)d_out;

    int N = in_sizes[0] / 16;   // 100000
    int E = in_sizes[1] / 2;    // 1600000

    void *dis_p, *g_p;
    cudaGetSymbolAddress(&dis_p, d_dis);
    cudaGetSymbolAddress(&g_p, d_g);

    int nb = (N + 2047) / 2048;
    int eb4 = (E + 4 * 256 - 1) / (4 * 256);
    int gblocks = (int)(((long long)N * 32 + 255) / 256);
    int gemmblocks = (N + 127) / 128;

    cudaStream_t s2;
    cudaStreamCreateWithFlags(&s2, cudaStreamNonBlocking);
    cudaEvent_t evF, evJ;
    cudaEventCreateWithFlags(&evF, cudaEventDisableTiming);
    cudaEventCreateWithFlags(&evJ, cudaEventDisableTiming);

    cudaEventRecord(evF, 0);
    cudaStreamWaitEvent(s2, evF, 0);

    // side stream: CSR construction
    cudaMemsetAsync(dis_p, 0, (size_t)N * sizeof(float), s2);
    detect_kernel<<<1, 32, 0, s2>>>((const int*)ei, E);
    degree_kernel<<<eb4, 256, 0, s2>>>(ei, E);
    scan_part<<<nb, 1024, 0, s2>>>(N);
    scan_apply<<<(N + 255) / 256, 256, 0, s2>>>(N, E, nb);
    place_kernel<<<eb4, 256, 0, s2>>>(ei, E);
    cudaEventRecord(evJ, s2);

    // main stream: dense track
    cudaMemsetAsync(g_p, 0, H * sizeof(float));
    wprep_kernel<<<48, 256>>>(conv_w);
    embed_kernel<<<(N + 31) / 32, 128>>>(x, emb_w, emb_b, N);
    gemm_mma_kernel<<<gemmblocks, 256>>>(0);

    cudaStreamWaitEvent(0, evJ, 0);

    gather_kernel<<<gblocks, 256>>>(conv_b + 0 * H, N);
    for (int l = 1; l < 3; l++) {
        gemm_mma_kernel<<<gemmblocks, 256>>>(l);
        gather_kernel<<<gblocks, 256>>>(conv_b + (size_t)l * H, N);
    }

    colsum_kernel<<<512, 128>>>(N);
    head_kernel<<<1, 128>>>(fc1_w, fc1_b, fc2_w, fc2_b, out, N);
}